// round 2
// baseline (speedup 1.0000x reference)
#include <cuda_runtime.h>

// LCA layer:
//   b = x@W                                   [8192, 4096]
//   u1 = 0.1*b (step 1 is analytic: a(u0)=0)
//   9x: a = relu(u-0.1)
//       t1 = a@W^T                            [8192, 1024]
//       u  = 0.9u + 0.1*(b - t1@W + a*diagG)  (a@G = (a@W^T)@W - a*diagG)
//   out = relu(u-0.1) @ W^T                   [8192, 1024]

static constexpr int NROWS  = 8192;
static constexpr int DMODEL = 1024;
static constexpr int DLCA   = 4096;
static constexpr float LAMBDA = 0.1f;
static constexpr float BETA   = 0.1f;   // DT/TAU
static constexpr float ONE_MB = 0.9f;   // 1 - BETA

// Scratch (allocation-free rule: __device__ globals)
__device__ float g_b [(size_t)NROWS * DLCA];   // 128 MB
__device__ float g_u [(size_t)NROWS * DLCA];   // 128 MB
__device__ float g_t1[(size_t)NROWS * DMODEL]; //  32 MB
__device__ float g_diagG[DLCA];

// ---------------------------------------------------------------------------
// diagG[j] = sum_d W[d,j]^2
__global__ void diag_kernel(const float* __restrict__ W) {
    int j = blockIdx.x * blockDim.x + threadIdx.x;
    if (j < DLCA) {
        float s = 0.f;
        #pragma unroll 8
        for (int d = 0; d < DMODEL; ++d) {
            float w = W[d * DLCA + j];
            s = fmaf(w, w, s);
        }
        g_diagG[j] = s;
    }
}

// u = BETA * b (vectorized)
__global__ void init_u_kernel() {
    size_t i = ((size_t)blockIdx.x * blockDim.x + threadIdx.x) * 4;
    float4 v = *reinterpret_cast<const float4*>(&g_b[i]);
    v.x *= BETA; v.y *= BETA; v.z *= BETA; v.w *= BETA;
    *reinterpret_cast<float4*>(&g_u[i]) = v;
}

// ---------------------------------------------------------------------------
// NN GEMM: C[m,n] = sum_k A[m,K..]*B[k,N..].  BM=BN=128, BK=16, 256 thr, 8x8/thr.
// MODE 0: C = A@B
// MODE 1: LCA update epilogue: u = 0.9u + 0.1*(b - acc + relu(u-l)*diagG)  (C unused)
template<int MODE>
__global__ __launch_bounds__(256)
void gemm_nn(const float* __restrict__ A, const float* __restrict__ B,
             float* __restrict__ C, int M, int K, int N)
{
    __shared__ float As[16][132];
    __shared__ float Bs[16][132];

    const int tid = threadIdx.x;
    const int rowBase = blockIdx.y * 128;
    const int colBase = blockIdx.x * 128;

    const int a_m  = tid >> 2;          // 0..63 (+64)
    const int a_k4 = (tid & 3) * 4;
    const int b_k  = tid >> 5;          // 0..7 (+8)
    const int b_n4 = (tid & 31) * 4;

    const int row0 = (tid >> 4) << 3;
    const int col0 = (tid & 15) << 3;

    float acc[8][8];
    #pragma unroll
    for (int i = 0; i < 8; ++i)
        #pragma unroll
        for (int j = 0; j < 8; ++j) acc[i][j] = 0.f;

    for (int kk = 0; kk < K; kk += 16) {
        // A tile: 128 rows x 16 k, stored transposed As[k][m]
        #pragma unroll
        for (int h = 0; h < 2; ++h) {
            int m = a_m + h * 64;
            float4 v = *reinterpret_cast<const float4*>(&A[(size_t)(rowBase + m) * K + kk + a_k4]);
            As[a_k4 + 0][m] = v.x;
            As[a_k4 + 1][m] = v.y;
            As[a_k4 + 2][m] = v.z;
            As[a_k4 + 3][m] = v.w;
        }
        // B tile: 16 k x 128 n, natural layout Bs[k][n]
        #pragma unroll
        for (int h = 0; h < 2; ++h) {
            int kr = b_k + h * 8;
            float4 v = *reinterpret_cast<const float4*>(&B[(size_t)(kk + kr) * N + colBase + b_n4]);
            *reinterpret_cast<float4*>(&Bs[kr][b_n4]) = v;
        }
        __syncthreads();

        #pragma unroll
        for (int k = 0; k < 16; ++k) {
            float4 a0 = *reinterpret_cast<const float4*>(&As[k][row0]);
            float4 a1 = *reinterpret_cast<const float4*>(&As[k][row0 + 4]);
            float4 b0 = *reinterpret_cast<const float4*>(&Bs[k][col0]);
            float4 b1 = *reinterpret_cast<const float4*>(&Bs[k][col0 + 4]);
            float ar[8] = {a0.x, a0.y, a0.z, a0.w, a1.x, a1.y, a1.z, a1.w};
            float br[8] = {b0.x, b0.y, b0.z, b0.w, b1.x, b1.y, b1.z, b1.w};
            #pragma unroll
            for (int i = 0; i < 8; ++i)
                #pragma unroll
                for (int j = 0; j < 8; ++j)
                    acc[i][j] = fmaf(ar[i], br[j], acc[i][j]);
        }
        __syncthreads();
    }

    if (MODE == 0) {
        #pragma unroll
        for (int i = 0; i < 8; ++i) {
            size_t base = (size_t)(rowBase + row0 + i) * N + colBase + col0;
            float4 v0 = make_float4(acc[i][0], acc[i][1], acc[i][2], acc[i][3]);
            float4 v1 = make_float4(acc[i][4], acc[i][5], acc[i][6], acc[i][7]);
            *reinterpret_cast<float4*>(&C[base])     = v0;
            *reinterpret_cast<float4*>(&C[base + 4]) = v1;
        }
    } else {
        int gc = colBase + col0;
        float4 dg0 = *reinterpret_cast<const float4*>(&g_diagG[gc]);
        float4 dg1 = *reinterpret_cast<const float4*>(&g_diagG[gc + 4]);
        float dg[8] = {dg0.x, dg0.y, dg0.z, dg0.w, dg1.x, dg1.y, dg1.z, dg1.w};
        #pragma unroll
        for (int i = 0; i < 8; ++i) {
            size_t base = (size_t)(rowBase + row0 + i) * N + gc;
            float4 u0 = *reinterpret_cast<const float4*>(&g_u[base]);
            float4 u1 = *reinterpret_cast<const float4*>(&g_u[base + 4]);
            float4 bb0 = *reinterpret_cast<const float4*>(&g_b[base]);
            float4 bb1 = *reinterpret_cast<const float4*>(&g_b[base + 4]);
            float uu[8] = {u0.x, u0.y, u0.z, u0.w, u1.x, u1.y, u1.z, u1.w};
            float bbv[8] = {bb0.x, bb0.y, bb0.z, bb0.w, bb1.x, bb1.y, bb1.z, bb1.w};
            float un[8];
            #pragma unroll
            for (int j = 0; j < 8; ++j) {
                float a = fmaxf(uu[j] - LAMBDA, 0.f);
                un[j] = ONE_MB * uu[j] + BETA * (bbv[j] - acc[i][j] + a * dg[j]);
            }
            *reinterpret_cast<float4*>(&g_u[base])     = make_float4(un[0], un[1], un[2], un[3]);
            *reinterpret_cast<float4*>(&g_u[base + 4]) = make_float4(un[4], un[5], un[6], un[7]);
        }
    }
}

// ---------------------------------------------------------------------------
// TN GEMM with fused relu on A:
//   C[m,n] = sum_k relu(A[m*K+k]-LAMBDA) * B[n*K+k]
// (used for t1 = a@W^T and out = a@W^T; B rows are W rows)
__global__ __launch_bounds__(256)
void gemm_tn_relu(const float* __restrict__ A, const float* __restrict__ B,
                  float* __restrict__ C, int M, int K, int N)
{
    __shared__ float As[16][132];
    __shared__ float Bs[16][132];

    const int tid = threadIdx.x;
    const int rowBase = blockIdx.y * 128;
    const int colBase = blockIdx.x * 128;

    const int a_m  = tid >> 2;          // 0..63 (+64)
    const int a_k4 = (tid & 3) * 4;

    const int row0 = (tid >> 4) << 3;
    const int col0 = (tid & 15) << 3;

    float acc[8][8];
    #pragma unroll
    for (int i = 0; i < 8; ++i)
        #pragma unroll
        for (int j = 0; j < 8; ++j) acc[i][j] = 0.f;

    for (int kk = 0; kk < K; kk += 16) {
        // A tile with fused relu(·-lambda): As[k][m]
        #pragma unroll
        for (int h = 0; h < 2; ++h) {
            int m = a_m + h * 64;
            float4 v = *reinterpret_cast<const float4*>(&A[(size_t)(rowBase + m) * K + kk + a_k4]);
            As[a_k4 + 0][m] = fmaxf(v.x - LAMBDA, 0.f);
            As[a_k4 + 1][m] = fmaxf(v.y - LAMBDA, 0.f);
            As[a_k4 + 2][m] = fmaxf(v.z - LAMBDA, 0.f);
            As[a_k4 + 3][m] = fmaxf(v.w - LAMBDA, 0.f);
        }
        // B tile (B is row-major [N,K] here): Bs[k][n]
        #pragma unroll
        for (int h = 0; h < 2; ++h) {
            int n = a_m + h * 64;
            float4 v = *reinterpret_cast<const float4*>(&B[(size_t)(colBase + n) * K + kk + a_k4]);
            Bs[a_k4 + 0][n] = v.x;
            Bs[a_k4 + 1][n] = v.y;
            Bs[a_k4 + 2][n] = v.z;
            Bs[a_k4 + 3][n] = v.w;
        }
        __syncthreads();

        #pragma unroll
        for (int k = 0; k < 16; ++k) {
            float4 a0 = *reinterpret_cast<const float4*>(&As[k][row0]);
            float4 a1 = *reinterpret_cast<const float4*>(&As[k][row0 + 4]);
            float4 b0 = *reinterpret_cast<const float4*>(&Bs[k][col0]);
            float4 b1 = *reinterpret_cast<const float4*>(&Bs[k][col0 + 4]);
            float ar[8] = {a0.x, a0.y, a0.z, a0.w, a1.x, a1.y, a1.z, a1.w};
            float br[8] = {b0.x, b0.y, b0.z, b0.w, b1.x, b1.y, b1.z, b1.w};
            #pragma unroll
            for (int i = 0; i < 8; ++i)
                #pragma unroll
                for (int j = 0; j < 8; ++j)
                    acc[i][j] = fmaf(ar[i], br[j], acc[i][j]);
        }
        __syncthreads();
    }

    #pragma unroll
    for (int i = 0; i < 8; ++i) {
        size_t base = (size_t)(rowBase + row0 + i) * N + colBase + col0;
        *reinterpret_cast<float4*>(&C[base])     = make_float4(acc[i][0], acc[i][1], acc[i][2], acc[i][3]);
        *reinterpret_cast<float4*>(&C[base + 4]) = make_float4(acc[i][4], acc[i][5], acc[i][6], acc[i][7]);
    }
}

// ---------------------------------------------------------------------------
extern "C" void kernel_launch(void* const* d_in, const int* in_sizes, int n_in,
                              void* d_out, int out_size)
{
    const float* x = (const float*)d_in[0];   // [8192, 1024] (4*2048 rows)
    const float* W = (const float*)d_in[1];   // [1024, 4096]
    float* out = (float*)d_out;               // [8192, 1024]

    float *pb, *pu, *pt1;
    cudaGetSymbolAddress((void**)&pb,  g_b);
    cudaGetSymbolAddress((void**)&pu,  g_u);
    cudaGetSymbolAddress((void**)&pt1, g_t1);

    // diagG
    diag_kernel<<<DLCA / 256, 256>>>(W);

    // b = x @ W
    gemm_nn<0><<<dim3(DLCA / 128, NROWS / 128), 256>>>(x, W, pb, NROWS, DMODEL, DLCA);

    // u = 0.1*b (analytic first step)
    init_u_kernel<<<(int)(((size_t)NROWS * DLCA) / (256 * 4)), 256>>>();

    // 9 remaining LCA steps
    for (int it = 0; it < 9; ++it) {
        // t1 = relu(u-lambda) @ W^T
        gemm_tn_relu<<<dim3(DMODEL / 128, NROWS / 128), 256>>>(pu, W, pt1, NROWS, DLCA, DMODEL);
        // u = 0.9u + 0.1*(b - t1@W + relu(u-lambda)*diagG)
        gemm_nn<1><<<dim3(DLCA / 128, NROWS / 128), 256>>>(pt1, W, nullptr, NROWS, DMODEL, DLCA);
    }

    // out = relu(u-lambda) @ W^T
    gemm_tn_relu<<<dim3(DMODEL / 128, NROWS / 128), 256>>>(pu, W, out, NROWS, DLCA, DMODEL);
}

// round 4
// speedup vs baseline: 1.8560x; 1.8560x over previous
#include <cuda_runtime.h>
#include <cuda_bf16.h>
#include <cstdint>

// LCA layer via mma.sync bf16 split-GEMMs (tcgen05 unavailable: harness PTX
// targets sm_103 without the 'a' feature suffix — HMMA path instead):
//   b = x@W ;  u1 = 0.1*b (analytic step 1)
//   9x: a = relu(u-0.1); t1 = a@W^T; u = 0.9u + 0.1*(b - t1@W + a*diagG)
//   out = relu(u-0.1) @ W^T
// float operands split v = hi + lo (bf16); GEMM computes Ah*Bh + Ah*Bl + Al*Bh.

static constexpr int NROWS  = 8192;
static constexpr int DMODEL = 1024;
static constexpr int DLCA   = 4096;
static constexpr float LAMBDA = 0.1f;
static constexpr float BETA   = 0.1f;
static constexpr float ONE_MB = 0.9f;

// ---------------------------------------------------------------- scratch
__device__ float g_b [(size_t)NROWS * DLCA];
__device__ float g_u [(size_t)NROWS * DLCA];
__device__ __nv_bfloat16 g_ahi[(size_t)NROWS * DLCA];
__device__ __nv_bfloat16 g_alo[(size_t)NROWS * DLCA];
__device__ __nv_bfloat16 g_t1hi[(size_t)NROWS * DMODEL];
__device__ __nv_bfloat16 g_t1lo[(size_t)NROWS * DMODEL];
__device__ __nv_bfloat16 g_xhi[(size_t)NROWS * DMODEL];
__device__ __nv_bfloat16 g_xlo[(size_t)NROWS * DMODEL];
__device__ __nv_bfloat16 g_Whi[(size_t)DMODEL * DLCA];
__device__ __nv_bfloat16 g_Wlo[(size_t)DMODEL * DLCA];
__device__ __nv_bfloat16 g_Wthi[(size_t)DLCA * DMODEL];
__device__ __nv_bfloat16 g_Wtlo[(size_t)DLCA * DMODEL];
__device__ float g_diagG[DLCA];

// ---------------------------------------------------------------- asm helpers
__device__ __forceinline__ uint32_t smem_u32(const void* p) {
    uint32_t a;
    asm("{ .reg .u64 t; cvta.to.shared.u64 t, %1; cvt.u32.u64 %0, t; }" : "=r"(a) : "l"(p));
    return a;
}
__device__ __forceinline__ void cp16(uint32_t dst, const void* src) {
    asm volatile("cp.async.cg.shared.global [%0], [%1], 16;" :: "r"(dst), "l"(src));
}
__device__ __forceinline__ void cp_commit() {
    asm volatile("cp.async.commit_group;" ::: "memory");
}
template <int N>
__device__ __forceinline__ void cp_wait() {
    asm volatile("cp.async.wait_group %0;" :: "n"(N) : "memory");
}
__device__ __forceinline__ void ldsm4(uint32_t* r, uint32_t addr) {
    asm volatile("ldmatrix.sync.aligned.m8n8.x4.shared.b16 {%0,%1,%2,%3}, [%4];"
                 : "=r"(r[0]), "=r"(r[1]), "=r"(r[2]), "=r"(r[3]) : "r"(addr));
}
__device__ __forceinline__ void mma_bf16(float* c, const uint32_t* a,
                                         uint32_t b0, uint32_t b1) {
    asm volatile(
        "mma.sync.aligned.m16n8k16.row.col.f32.bf16.bf16.f32 "
        "{%0,%1,%2,%3}, {%4,%5,%6,%7}, {%8,%9}, {%0,%1,%2,%3};"
        : "+f"(c[0]), "+f"(c[1]), "+f"(c[2]), "+f"(c[3])
        : "r"(a[0]), "r"(a[1]), "r"(a[2]), "r"(a[3]), "r"(b0), "r"(b1));
}

// ---------------------------------------------------------------- prep kernels
__global__ void diag_kernel(const float* __restrict__ W) {
    int j = blockIdx.x * blockDim.x + threadIdx.x;
    if (j < DLCA) {
        float s = 0.f;
        #pragma unroll 8
        for (int d = 0; d < DMODEL; ++d) {
            float w = W[(size_t)d * DLCA + j];
            s = fmaf(w, w, s);
        }
        g_diagG[j] = s;
    }
}

__global__ void split_kernel(const float* __restrict__ src,
                             __nv_bfloat16* __restrict__ hi,
                             __nv_bfloat16* __restrict__ lo) {
    size_t i = ((size_t)blockIdx.x * blockDim.x + threadIdx.x) * 4;
    float4 v = *reinterpret_cast<const float4*>(src + i);
    float vv[4] = {v.x, v.y, v.z, v.w};
    __nv_bfloat162 hp[2], lp[2];
    #pragma unroll
    for (int j = 0; j < 2; ++j) {
        __nv_bfloat16 h0 = __float2bfloat16(vv[2*j]);
        __nv_bfloat16 h1 = __float2bfloat16(vv[2*j+1]);
        hp[j] = __halves2bfloat162(h0, h1);
        lp[j] = __halves2bfloat162(__float2bfloat16(vv[2*j]   - __bfloat162float(h0)),
                                   __float2bfloat16(vv[2*j+1] - __bfloat162float(h1)));
    }
    *reinterpret_cast<uint2*>(hi + i) = *reinterpret_cast<const uint2*>(hp);
    *reinterpret_cast<uint2*>(lo + i) = *reinterpret_cast<const uint2*>(lp);
}

__global__ void transpose_split_kernel(const float* __restrict__ W) {
    __shared__ float tile[32][33];
    int bx = blockIdx.x * 32;   // n
    int by = blockIdx.y * 32;   // d
    for (int i = threadIdx.y; i < 32; i += 8)
        tile[i][threadIdx.x] = W[(size_t)(by + i) * DLCA + bx + threadIdx.x];
    __syncthreads();
    for (int i = threadIdx.y; i < 32; i += 8) {
        int n = bx + i;
        int d = by + threadIdx.x;
        float v = tile[threadIdx.x][i];
        __nv_bfloat16 h = __float2bfloat16(v);
        g_Wthi[(size_t)n * DMODEL + d] = h;
        g_Wtlo[(size_t)n * DMODEL + d] = __float2bfloat16(v - __bfloat162float(h));
    }
}

// ---------------------------------------------------------------- main GEMM
// C tile 128x128; A row-major [M,K], B row-major [N,K] (TN). BK=32 bf16.
// SMEM tile rows padded to 80B (40 bf16) -> conflict-free ldmatrix.
// Stage = {Ah, Al, Bh, Bl} tiles of 128 x 32 bf16 each. 3 stages, cp.async.
static constexpr int ROWB        = 80;       // bytes per smem row
static constexpr int TILE_BYTES  = 128 * ROWB;   // 10240
static constexpr int STAGE_BYTES = 4 * TILE_BYTES;
static constexpr int NSTAGE      = 3;
static constexpr int SMEM_TOTAL  = NSTAGE * STAGE_BYTES;   // 122880

__device__ __forceinline__ void stage_load(uint32_t sb,
        const __nv_bfloat16* __restrict__ Ah, const __nv_bfloat16* __restrict__ Al,
        const __nv_bfloat16* __restrict__ Bh, const __nv_bfloat16* __restrict__ Bl,
        int rowBase, int colBase, int k0, int K, int tid) {
    #pragma unroll
    for (int i = 0; i < 2; ++i) {
        int c = tid + i * 256;
        int r = c >> 2, cc = c & 3;
        uint32_t so = (uint32_t)(r * ROWB + cc * 16);
        size_t ga = (size_t)(rowBase + r) * K + k0 + cc * 8;
        size_t gb = (size_t)(colBase + r) * K + k0 + cc * 8;
        cp16(sb + so,                  Ah + ga);
        cp16(sb + TILE_BYTES + so,     Al + ga);
        cp16(sb + 2 * TILE_BYTES + so, Bh + gb);
        cp16(sb + 3 * TILE_BYTES + so, Bl + gb);
    }
}

// EPI: 0 = b-init, 1 = t1-split, 2 = LCA update, 3 = out fp32
template <int EPI>
__global__ void __launch_bounds__(256, 1)
lca_gemm(const __nv_bfloat16* __restrict__ Ah, const __nv_bfloat16* __restrict__ Al,
         const __nv_bfloat16* __restrict__ Bh, const __nv_bfloat16* __restrict__ Bl,
         int K, float* __restrict__ outp) {
    extern __shared__ __align__(256) char smem[];
    const uint32_t sbase = smem_u32(smem);
    const int tid = threadIdx.x;
    const int wid = tid >> 5;
    const int lid = tid & 31;
    const int warpM = wid >> 2;          // 0..1  (m offset 64)
    const int warpN = wid & 3;           // 0..3  (n offset 32)
    const int rowBase = blockIdx.y * 128;
    const int colBase = blockIdx.x * 128;
    const int KT = K >> 5;

    float acc[4][4][4];
    #pragma unroll
    for (int mi = 0; mi < 4; ++mi)
        #pragma unroll
        for (int ni = 0; ni < 4; ++ni)
            #pragma unroll
            for (int q = 0; q < 4; ++q) acc[mi][ni][q] = 0.f;

    // prologue: stages 0,1
    stage_load(sbase, Ah, Al, Bh, Bl, rowBase, colBase, 0, K, tid);
    cp_commit();
    stage_load(sbase + STAGE_BYTES, Ah, Al, Bh, Bl, rowBase, colBase, 32, K, tid);
    cp_commit();

    // ldmatrix lane addressing
    const uint32_t lrow = (uint32_t)(lid & 15);
    const uint32_t lcol = (uint32_t)((lid >> 4) * 16);

    int sidx = 0;
    for (int kt = 0; kt < KT; ++kt) {
        cp_wait<1>();
        __syncthreads();

        if (kt + 2 < KT)
            stage_load(sbase + ((sidx + 2) % NSTAGE) * STAGE_BYTES,
                       Ah, Al, Bh, Bl, rowBase, colBase, (kt + 2) * 32, K, tid);
        cp_commit();

        const uint32_t sb = sbase + sidx * STAGE_BYTES;
        const uint32_t aBase = sb + (uint32_t)(warpM * 64) * ROWB;
        const uint32_t bBase = sb + 2 * TILE_BYTES + (uint32_t)(warpN * 32) * ROWB;

        #pragma unroll
        for (int ks = 0; ks < 2; ++ks) {
            const uint32_t kb = (uint32_t)(ks * 32) + lcol;
            uint32_t ah[4][4], al[4][4], bh[2][4], bl[2][4];
            #pragma unroll
            for (int mi = 0; mi < 4; ++mi) {
                uint32_t ad = aBase + (uint32_t)(mi * 16 + lrow) * ROWB + kb;
                ldsm4(ah[mi], ad);
                ldsm4(al[mi], ad + TILE_BYTES);
            }
            #pragma unroll
            for (int nj = 0; nj < 2; ++nj) {
                uint32_t bd = bBase + (uint32_t)(nj * 16 + lrow) * ROWB + kb;
                ldsm4(bh[nj], bd);
                ldsm4(bl[nj], bd + TILE_BYTES);
            }
            #pragma unroll
            for (int mi = 0; mi < 4; ++mi)
                #pragma unroll
                for (int ni = 0; ni < 4; ++ni) {
                    const int nj = ni >> 1, nr = ni & 1;
                    mma_bf16(acc[mi][ni], ah[mi], bh[nj][nr],     bh[nj][nr + 2]);
                    mma_bf16(acc[mi][ni], ah[mi], bl[nj][nr],     bl[nj][nr + 2]);
                    mma_bf16(acc[mi][ni], al[mi], bh[nj][nr],     bh[nj][nr + 2]);
                }
        }
        __syncthreads();
        sidx = (sidx + 1) % NSTAGE;
    }

    // ------------------------------------------------------------ epilogue
    const int qrow = lid >> 2;
    const int qcol = (lid & 3) * 2;
    const int ldo = (EPI == 1 || EPI == 3) ? DMODEL : DLCA;

    #pragma unroll
    for (int mi = 0; mi < 4; ++mi) {
        #pragma unroll
        for (int ni = 0; ni < 4; ++ni) {
            const int r0 = rowBase + warpM * 64 + mi * 16 + qrow;
            const int c  = colBase + warpN * 32 + ni * 8 + qcol;
            #pragma unroll
            for (int h = 0; h < 2; ++h) {
                const int r = r0 + h * 8;
                const size_t base = (size_t)r * ldo + c;
                const float v0 = acc[mi][ni][2*h], v1 = acc[mi][ni][2*h + 1];
                if (EPI == 0) {
                    float u0 = BETA * v0, u1 = BETA * v1;
                    *reinterpret_cast<float2*>(g_b + base) = make_float2(v0, v1);
                    *reinterpret_cast<float2*>(g_u + base) = make_float2(u0, u1);
                    float a0 = fmaxf(u0 - LAMBDA, 0.f), a1 = fmaxf(u1 - LAMBDA, 0.f);
                    __nv_bfloat16 h0 = __float2bfloat16(a0), h1 = __float2bfloat16(a1);
                    *reinterpret_cast<__nv_bfloat162*>(g_ahi + base) = __halves2bfloat162(h0, h1);
                    *reinterpret_cast<__nv_bfloat162*>(g_alo + base) =
                        __halves2bfloat162(__float2bfloat16(a0 - __bfloat162float(h0)),
                                           __float2bfloat16(a1 - __bfloat162float(h1)));
                } else if (EPI == 2) {
                    float2 uo = *reinterpret_cast<const float2*>(g_u + base);
                    float2 bv = *reinterpret_cast<const float2*>(g_b + base);
                    float2 dg = *reinterpret_cast<const float2*>(g_diagG + c);
                    float ao0 = fmaxf(uo.x - LAMBDA, 0.f), ao1 = fmaxf(uo.y - LAMBDA, 0.f);
                    float u0 = ONE_MB * uo.x + BETA * (bv.x - v0 + ao0 * dg.x);
                    float u1 = ONE_MB * uo.y + BETA * (bv.y - v1 + ao1 * dg.y);
                    *reinterpret_cast<float2*>(g_u + base) = make_float2(u0, u1);
                    float a0 = fmaxf(u0 - LAMBDA, 0.f), a1 = fmaxf(u1 - LAMBDA, 0.f);
                    __nv_bfloat16 h0 = __float2bfloat16(a0), h1 = __float2bfloat16(a1);
                    *reinterpret_cast<__nv_bfloat162*>(g_ahi + base) = __halves2bfloat162(h0, h1);
                    *reinterpret_cast<__nv_bfloat162*>(g_alo + base) =
                        __halves2bfloat162(__float2bfloat16(a0 - __bfloat162float(h0)),
                                           __float2bfloat16(a1 - __bfloat162float(h1)));
                } else if (EPI == 1) {
                    __nv_bfloat16 h0 = __float2bfloat16(v0), h1 = __float2bfloat16(v1);
                    *reinterpret_cast<__nv_bfloat162*>(g_t1hi + base) = __halves2bfloat162(h0, h1);
                    *reinterpret_cast<__nv_bfloat162*>(g_t1lo + base) =
                        __halves2bfloat162(__float2bfloat16(v0 - __bfloat162float(h0)),
                                           __float2bfloat16(v1 - __bfloat162float(h1)));
                } else {
                    *reinterpret_cast<float2*>(outp + base) = make_float2(v0, v1);
                }
            }
        }
    }
}

// ---------------------------------------------------------------- launch
extern "C" void kernel_launch(void* const* d_in, const int* in_sizes, int n_in,
                              void* d_out, int out_size) {
    const float* x = (const float*)d_in[0];   // [8192, 1024]
    const float* W = (const float*)d_in[1];   // [1024, 4096]
    float* out = (float*)d_out;               // [8192, 1024]

    __nv_bfloat16 *xhi, *xlo, *Whi, *Wlo, *Wthi, *Wtlo, *ahi, *alo, *t1hi, *t1lo;
    cudaGetSymbolAddress((void**)&xhi,  g_xhi);
    cudaGetSymbolAddress((void**)&xlo,  g_xlo);
    cudaGetSymbolAddress((void**)&Whi,  g_Whi);
    cudaGetSymbolAddress((void**)&Wlo,  g_Wlo);
    cudaGetSymbolAddress((void**)&Wthi, g_Wthi);
    cudaGetSymbolAddress((void**)&Wtlo, g_Wtlo);
    cudaGetSymbolAddress((void**)&ahi,  g_ahi);
    cudaGetSymbolAddress((void**)&alo,  g_alo);
    cudaGetSymbolAddress((void**)&t1hi, g_t1hi);
    cudaGetSymbolAddress((void**)&t1lo, g_t1lo);

    cudaFuncSetAttribute(lca_gemm<0>, cudaFuncAttributeMaxDynamicSharedMemorySize, SMEM_TOTAL);
    cudaFuncSetAttribute(lca_gemm<1>, cudaFuncAttributeMaxDynamicSharedMemorySize, SMEM_TOTAL);
    cudaFuncSetAttribute(lca_gemm<2>, cudaFuncAttributeMaxDynamicSharedMemorySize, SMEM_TOTAL);
    cudaFuncSetAttribute(lca_gemm<3>, cudaFuncAttributeMaxDynamicSharedMemorySize, SMEM_TOTAL);

    // prep
    split_kernel<<<(int)(((size_t)NROWS * DMODEL) / 1024), 256>>>(x, xhi, xlo);
    split_kernel<<<(int)(((size_t)DMODEL * DLCA) / 1024), 256>>>(W, Whi, Wlo);
    transpose_split_kernel<<<dim3(DLCA / 32, DMODEL / 32), dim3(32, 8)>>>(W);
    diag_kernel<<<DLCA / 256, 256>>>(W);

    // b = x@W ; u = 0.1b ; a = relu(u - lambda) (split)
    lca_gemm<0><<<dim3(DLCA / 128, NROWS / 128), 256, SMEM_TOTAL>>>(
        xhi, xlo, Wthi, Wtlo, DMODEL, nullptr);

    for (int it = 0; it < 9; ++it) {
        // t1 = a @ W^T (split output)
        lca_gemm<1><<<dim3(DMODEL / 128, NROWS / 128), 256, SMEM_TOTAL>>>(
            ahi, alo, Whi, Wlo, DLCA, nullptr);
        // u = 0.9u + 0.1(b - t1@W + a*diagG) ; a = relu(u - lambda) (split)
        lca_gemm<2><<<dim3(DLCA / 128, NROWS / 128), 256, SMEM_TOTAL>>>(
            t1hi, t1lo, Wthi, Wtlo, DMODEL, nullptr);
    }

    // out = a @ W^T (fp32)
    lca_gemm<3><<<dim3(DMODEL / 128, NROWS / 128), 256, SMEM_TOTAL>>>(
        ahi, alo, Whi, Wlo, DLCA, out);
}

// round 5
// speedup vs baseline: 2.8947x; 1.5596x over previous
#include <cuda_runtime.h>
#include <cuda_fp16.h>
#include <cstdint>

// LCA layer via mma.sync fp16 split-GEMMs.
//   b = x@W ;  u1 = 0.1*b (analytic step 1)
//   9x: a = relu(u-0.1); t1 = a@W^T; u = 0.9u + 0.1*(b - t1@W + a*diagG)
//   out = relu(u-0.1) @ W^T
// A-side operands: exact 2-term fp16 split (hi+lo). W-side: single fp16 term
// inside the iterations (2 MMAs per product), 2-term for b and out (3 MMAs).
// diagG computed from fp16(W) so self-inhibition cancels exactly.

static constexpr int NROWS  = 8192;
static constexpr int DMODEL = 1024;
static constexpr int DLCA   = 4096;
static constexpr float LAMBDA = 0.1f;
static constexpr float BETA   = 0.1f;
static constexpr float ONE_MB = 0.9f;

// ---------------------------------------------------------------- scratch
__device__ float g_b [(size_t)NROWS * DLCA];
__device__ float g_u [(size_t)NROWS * DLCA];
__device__ __half g_ahi[(size_t)NROWS * DLCA];
__device__ __half g_alo[(size_t)NROWS * DLCA];
__device__ __half g_t1hi[(size_t)NROWS * DMODEL];
__device__ __half g_t1lo[(size_t)NROWS * DMODEL];
__device__ __half g_xhi[(size_t)NROWS * DMODEL];
__device__ __half g_xlo[(size_t)NROWS * DMODEL];
__device__ __half g_Whi[(size_t)DMODEL * DLCA];   // [d, n] row-major
__device__ __half g_Wlo[(size_t)DMODEL * DLCA];
__device__ __half g_Wthi[(size_t)DLCA * DMODEL];  // [n, d] row-major
__device__ __half g_Wtlo[(size_t)DLCA * DMODEL];
__device__ float g_diagG[DLCA];

// ---------------------------------------------------------------- asm helpers
__device__ __forceinline__ uint32_t smem_u32(const void* p) {
    uint32_t a;
    asm("{ .reg .u64 t; cvta.to.shared.u64 t, %1; cvt.u32.u64 %0, t; }" : "=r"(a) : "l"(p));
    return a;
}
__device__ __forceinline__ void cp16(uint32_t dst, const void* src) {
    asm volatile("cp.async.cg.shared.global [%0], [%1], 16;" :: "r"(dst), "l"(src));
}
__device__ __forceinline__ void cp_commit() {
    asm volatile("cp.async.commit_group;" ::: "memory");
}
template <int N>
__device__ __forceinline__ void cp_wait() {
    asm volatile("cp.async.wait_group %0;" :: "n"(N) : "memory");
}
__device__ __forceinline__ void ldsm4(uint32_t* r, uint32_t addr) {
    asm volatile("ldmatrix.sync.aligned.m8n8.x4.shared.b16 {%0,%1,%2,%3}, [%4];"
                 : "=r"(r[0]), "=r"(r[1]), "=r"(r[2]), "=r"(r[3]) : "r"(addr));
}
__device__ __forceinline__ void mma_f16(float* c, const uint32_t* a,
                                        uint32_t b0, uint32_t b1) {
    asm volatile(
        "mma.sync.aligned.m16n8k16.row.col.f32.f16.f16.f32 "
        "{%0,%1,%2,%3}, {%4,%5,%6,%7}, {%8,%9}, {%0,%1,%2,%3};"
        : "+f"(c[0]), "+f"(c[1]), "+f"(c[2]), "+f"(c[3])
        : "r"(a[0]), "r"(a[1]), "r"(a[2]), "r"(a[3]), "r"(b0), "r"(b1));
}

// ---------------------------------------------------------------- prep kernels
__global__ void zero_diag_kernel() {
    int i = blockIdx.x * blockDim.x + threadIdx.x;
    if (i < DLCA) g_diagG[i] = 0.f;
}
// diagG[n] = sum_d fp16(W)[d,n]^2, parallel over 8 d-chunks with atomicAdd
__global__ void diag_kernel() {
    int n  = blockIdx.x * 512 + threadIdx.x;
    int d0 = blockIdx.y * 128;
    float s = 0.f;
    #pragma unroll 8
    for (int d = d0; d < d0 + 128; ++d) {
        float w = __half2float(g_Whi[(size_t)d * DLCA + n]);
        s = fmaf(w, w, s);
    }
    atomicAdd(&g_diagG[n], s);
}

__global__ void split_kernel(const float* __restrict__ src,
                             __half* __restrict__ hi, __half* __restrict__ lo) {
    size_t i = ((size_t)blockIdx.x * blockDim.x + threadIdx.x) * 4;
    float4 v = *reinterpret_cast<const float4*>(src + i);
    float vv[4] = {v.x, v.y, v.z, v.w};
    __half2 hp[2], lp[2];
    #pragma unroll
    for (int j = 0; j < 2; ++j) {
        __half h0 = __float2half_rn(vv[2*j]);
        __half h1 = __float2half_rn(vv[2*j+1]);
        hp[j] = __halves2half2(h0, h1);
        lp[j] = __halves2half2(__float2half_rn(vv[2*j]   - __half2float(h0)),
                               __float2half_rn(vv[2*j+1] - __half2float(h1)));
    }
    *reinterpret_cast<uint2*>(hi + i) = *reinterpret_cast<const uint2*>(hp);
    *reinterpret_cast<uint2*>(lo + i) = *reinterpret_cast<const uint2*>(lp);
}

__global__ void transpose_split_kernel(const float* __restrict__ W) {
    __shared__ float tile[32][33];
    int bx = blockIdx.x * 32;   // n
    int by = blockIdx.y * 32;   // d
    for (int i = threadIdx.y; i < 32; i += 8)
        tile[i][threadIdx.x] = W[(size_t)(by + i) * DLCA + bx + threadIdx.x];
    __syncthreads();
    for (int i = threadIdx.y; i < 32; i += 8) {
        int n = bx + i;
        int d = by + threadIdx.x;
        float v = tile[threadIdx.x][i];
        __half h = __float2half_rn(v);
        g_Wthi[(size_t)n * DMODEL + d] = h;
        g_Wtlo[(size_t)n * DMODEL + d] = __float2half_rn(v - __half2float(h));
    }
}

// ---------------------------------------------------------------- main GEMM
// C tile 128(M) x 256(N); A row-major [M,K] (2-term), B row-major [N,K]
// (1 or 2 term). BK=32 fp16. SMEM rows padded to 80B -> conflict-free ldmatrix.
// 16 warps as 4(M) x 4(N); warp tile 32 x 64. 3-stage cp.async pipeline.
static constexpr int ROWB   = 80;
static constexpr int A_TILE = 128 * ROWB;    // 10240
static constexpr int B_TILE = 256 * ROWB;    // 20480

template <int TERMS>
__device__ __forceinline__ void stage_load(uint32_t sb,
        const __half* __restrict__ Ah, const __half* __restrict__ Al,
        const __half* __restrict__ Bh, const __half* __restrict__ Bl,
        int rowBase, int colBase, int k0, int K, int tid) {
    {
        int r = tid >> 2, cc = tid & 3;
        uint32_t off = (uint32_t)(r * ROWB + cc * 16);
        size_t ga = (size_t)(rowBase + r) * K + k0 + cc * 8;
        cp16(sb + off,          Ah + ga);
        cp16(sb + A_TILE + off, Al + ga);
    }
    #pragma unroll
    for (int i = 0; i < 2; ++i) {
        int idx = tid + i * 512;
        int r = idx >> 2, cc = idx & 3;
        uint32_t off = (uint32_t)(r * ROWB + cc * 16);
        size_t gb = (size_t)(colBase + r) * K + k0 + cc * 8;
        cp16(sb + 2 * A_TILE + off, Bh + gb);
        if (TERMS == 3)
            cp16(sb + 2 * A_TILE + B_TILE + off, Bl + gb);
    }
}

// EPI: 0 = b-init, 1 = t1-split, 2 = LCA update, 3 = out fp32
template <int EPI, int TERMS>
__global__ void __launch_bounds__(512, 1)
lca_gemm(const __half* __restrict__ Ah, const __half* __restrict__ Al,
         const __half* __restrict__ Bh, const __half* __restrict__ Bl,
         int K, float* __restrict__ outp) {
    constexpr int STAGE_BYTES = 2 * A_TILE + ((TERMS == 3) ? 2 : 1) * B_TILE;
    extern __shared__ __align__(256) char smem[];
    const uint32_t sbase = smem_u32(smem);
    const int tid = threadIdx.x;
    const int wid = tid >> 5;
    const int lid = tid & 31;
    const int warpM = wid >> 2;          // 0..3  (m offset 32)
    const int warpN = wid & 3;           // 0..3  (n offset 64)
    const int rowBase = blockIdx.y * 128;
    const int colBase = blockIdx.x * 256;
    const int KT = K >> 5;

    float acc[2][8][4];
    #pragma unroll
    for (int mi = 0; mi < 2; ++mi)
        #pragma unroll
        for (int ni = 0; ni < 8; ++ni)
            #pragma unroll
            for (int q = 0; q < 4; ++q) acc[mi][ni][q] = 0.f;

    stage_load<TERMS>(sbase, Ah, Al, Bh, Bl, rowBase, colBase, 0, K, tid);
    cp_commit();
    stage_load<TERMS>(sbase + STAGE_BYTES, Ah, Al, Bh, Bl, rowBase, colBase, 32, K, tid);
    cp_commit();

    const uint32_t lrow = (uint32_t)(lid & 15);
    const uint32_t lcol = (uint32_t)((lid >> 4) * 16);

    int sidx = 0;
    for (int kt = 0; kt < KT; ++kt) {
        cp_wait<1>();
        __syncthreads();

        if (kt + 2 < KT)
            stage_load<TERMS>(sbase + ((sidx + 2) % 3) * STAGE_BYTES,
                              Ah, Al, Bh, Bl, rowBase, colBase, (kt + 2) * 32, K, tid);
        cp_commit();

        const uint32_t sb = sbase + sidx * STAGE_BYTES;
        const uint32_t aBase = sb + (uint32_t)(warpM * 32) * ROWB;
        const uint32_t bBase = sb + 2 * A_TILE + (uint32_t)(warpN * 64) * ROWB;

        #pragma unroll
        for (int ks = 0; ks < 2; ++ks) {
            const uint32_t kb = (uint32_t)(ks * 32) + lcol;
            uint32_t ah[2][4], al[2][4], bf[4][4];
            #pragma unroll
            for (int mi = 0; mi < 2; ++mi) {
                uint32_t ad = aBase + (uint32_t)(mi * 16 + lrow) * ROWB + kb;
                ldsm4(ah[mi], ad);
                ldsm4(al[mi], ad + A_TILE);
            }
            #pragma unroll
            for (int nj = 0; nj < 4; ++nj)
                ldsm4(bf[nj], bBase + (uint32_t)(nj * 16 + lrow) * ROWB + kb);

            #pragma unroll
            for (int mi = 0; mi < 2; ++mi)
                #pragma unroll
                for (int ni = 0; ni < 8; ++ni) {
                    const int nj = ni >> 1, nr = ni & 1;
                    mma_f16(acc[mi][ni], ah[mi], bf[nj][nr], bf[nj][nr + 2]);
                    mma_f16(acc[mi][ni], al[mi], bf[nj][nr], bf[nj][nr + 2]);
                }
            if (TERMS == 3) {
                #pragma unroll
                for (int nj = 0; nj < 4; ++nj)
                    ldsm4(bf[nj], bBase + B_TILE + (uint32_t)(nj * 16 + lrow) * ROWB + kb);
                #pragma unroll
                for (int mi = 0; mi < 2; ++mi)
                    #pragma unroll
                    for (int ni = 0; ni < 8; ++ni) {
                        const int nj = ni >> 1, nr = ni & 1;
                        mma_f16(acc[mi][ni], ah[mi], bf[nj][nr], bf[nj][nr + 2]);
                    }
            }
        }
        __syncthreads();
        sidx = (sidx + 1) % 3;
    }

    // ------------------------------------------------------------ epilogue
    const int qrow = lid >> 2;
    const int qcol = (lid & 3) * 2;
    const int ldo = (EPI == 1 || EPI == 3) ? DMODEL : DLCA;

    #pragma unroll
    for (int mi = 0; mi < 2; ++mi) {
        #pragma unroll
        for (int ni = 0; ni < 8; ++ni) {
            const int r0 = rowBase + warpM * 32 + mi * 16 + qrow;
            const int c  = colBase + warpN * 64 + ni * 8 + qcol;
            #pragma unroll
            for (int h = 0; h < 2; ++h) {
                const int r = r0 + h * 8;
                const size_t base = (size_t)r * ldo + c;
                const float v0 = acc[mi][ni][2*h], v1 = acc[mi][ni][2*h + 1];
                if (EPI == 0) {
                    float u0 = BETA * v0, u1 = BETA * v1;
                    *reinterpret_cast<float2*>(g_b + base) = make_float2(v0, v1);
                    *reinterpret_cast<float2*>(g_u + base) = make_float2(u0, u1);
                    float a0 = fmaxf(u0 - LAMBDA, 0.f), a1 = fmaxf(u1 - LAMBDA, 0.f);
                    __half h0 = __float2half_rn(a0), h1 = __float2half_rn(a1);
                    *reinterpret_cast<__half2*>(g_ahi + base) = __halves2half2(h0, h1);
                    *reinterpret_cast<__half2*>(g_alo + base) =
                        __halves2half2(__float2half_rn(a0 - __half2float(h0)),
                                       __float2half_rn(a1 - __half2float(h1)));
                } else if (EPI == 2) {
                    float2 uo = *reinterpret_cast<const float2*>(g_u + base);
                    float2 bv = *reinterpret_cast<const float2*>(g_b + base);
                    float2 dg = *reinterpret_cast<const float2*>(g_diagG + c);
                    float ao0 = fmaxf(uo.x - LAMBDA, 0.f), ao1 = fmaxf(uo.y - LAMBDA, 0.f);
                    float u0 = ONE_MB * uo.x + BETA * (bv.x - v0 + ao0 * dg.x);
                    float u1 = ONE_MB * uo.y + BETA * (bv.y - v1 + ao1 * dg.y);
                    *reinterpret_cast<float2*>(g_u + base) = make_float2(u0, u1);
                    float a0 = fmaxf(u0 - LAMBDA, 0.f), a1 = fmaxf(u1 - LAMBDA, 0.f);
                    __half h0 = __float2half_rn(a0), h1 = __float2half_rn(a1);
                    *reinterpret_cast<__half2*>(g_ahi + base) = __halves2half2(h0, h1);
                    *reinterpret_cast<__half2*>(g_alo + base) =
                        __halves2half2(__float2half_rn(a0 - __half2float(h0)),
                                       __float2half_rn(a1 - __half2float(h1)));
                } else if (EPI == 1) {
                    __half h0 = __float2half_rn(v0), h1 = __float2half_rn(v1);
                    *reinterpret_cast<__half2*>(g_t1hi + base) = __halves2half2(h0, h1);
                    *reinterpret_cast<__half2*>(g_t1lo + base) =
                        __halves2half2(__float2half_rn(v0 - __half2float(h0)),
                                       __float2half_rn(v1 - __half2float(h1)));
                } else {
                    *reinterpret_cast<float2*>(outp + base) = make_float2(v0, v1);
                }
            }
        }
    }
}

// ---------------------------------------------------------------- launch
extern "C" void kernel_launch(void* const* d_in, const int* in_sizes, int n_in,
                              void* d_out, int out_size) {
    const float* x = (const float*)d_in[0];   // [8192, 1024]
    const float* W = (const float*)d_in[1];   // [1024, 4096]
    float* out = (float*)d_out;               // [8192, 1024]

    __half *xhi, *xlo, *Whi, *Wlo, *Wthi, *Wtlo, *ahi, *alo, *t1hi, *t1lo;
    cudaGetSymbolAddress((void**)&xhi,  g_xhi);
    cudaGetSymbolAddress((void**)&xlo,  g_xlo);
    cudaGetSymbolAddress((void**)&Whi,  g_Whi);
    cudaGetSymbolAddress((void**)&Wlo,  g_Wlo);
    cudaGetSymbolAddress((void**)&Wthi, g_Wthi);
    cudaGetSymbolAddress((void**)&Wtlo, g_Wtlo);
    cudaGetSymbolAddress((void**)&ahi,  g_ahi);
    cudaGetSymbolAddress((void**)&alo,  g_alo);
    cudaGetSymbolAddress((void**)&t1hi, g_t1hi);
    cudaGetSymbolAddress((void**)&t1lo, g_t1lo);

    constexpr int SM2 = 3 * (2 * A_TILE + B_TILE);       // 122880
    constexpr int SM3 = 3 * (2 * A_TILE + 2 * B_TILE);   // 184320
    cudaFuncSetAttribute(lca_gemm<0,3>, cudaFuncAttributeMaxDynamicSharedMemorySize, SM3);
    cudaFuncSetAttribute(lca_gemm<1,2>, cudaFuncAttributeMaxDynamicSharedMemorySize, SM2);
    cudaFuncSetAttribute(lca_gemm<2,2>, cudaFuncAttributeMaxDynamicSharedMemorySize, SM2);
    cudaFuncSetAttribute(lca_gemm<3,3>, cudaFuncAttributeMaxDynamicSharedMemorySize, SM3);

    // prep
    split_kernel<<<(int)(((size_t)NROWS * DMODEL) / 1024), 256>>>(x, xhi, xlo);
    split_kernel<<<(int)(((size_t)DMODEL * DLCA) / 1024), 256>>>(W, Whi, Wlo);
    transpose_split_kernel<<<dim3(DLCA / 32, DMODEL / 32), dim3(32, 8)>>>(W);
    zero_diag_kernel<<<DLCA / 256, 256>>>();
    diag_kernel<<<dim3(DLCA / 512, 8), 512>>>();

    // b = x@W (3-term) ; u = 0.1b ; a = relu(u - lambda) split
    lca_gemm<0,3><<<dim3(DLCA / 256, NROWS / 128), 512, SM3>>>(
        xhi, xlo, Wthi, Wtlo, DMODEL, nullptr);

    for (int it = 0; it < 9; ++it) {
        // t1 = a @ W^T (2-term, split output)
        lca_gemm<1,2><<<dim3(DMODEL / 256, NROWS / 128), 512, SM2>>>(
            ahi, alo, Whi, nullptr, DLCA, nullptr);
        // u = 0.9u + 0.1(b - t1@W + a*diagG) ; a = relu(u - lambda) split
        lca_gemm<2,2><<<dim3(DLCA / 256, NROWS / 128), 512, SM2>>>(
            t1hi, t1lo, Wthi, nullptr, DMODEL, nullptr);
    }

    // out = a @ W^T (3-term, fp32)
    lca_gemm<3,3><<<dim3(DMODEL / 256, NROWS / 128), 512, SM3>>>(
        ahi, alo, Whi, Wlo, DLCA, out);
}

// round 6
// speedup vs baseline: 4.6745x; 1.6148x over previous
#include <cuda_runtime.h>
#include <cuda_fp16.h>
#include <cstdint>

// LCA layer via mma.sync fp16 split-GEMMs.
//   b = x@W ;  u1 = 0.1*b (analytic step 1)
//   9x: a = relu(u-0.1); t1 = a@W^T; u = 0.9u + 0.1*(b - t1@W + a*diagG)
//   out = relu(u-0.1) @ W^T
// Boundary GEMMs (b, out): 2-term fp16 splits on both operands (3 MMAs).
// Iteration GEMMs: single fp16 term on both operands (1 MMA) — fp16 rounding
// of a/t1 is a ~2^-12 perturbation of the dynamics, well under tolerance.
// diagG computed from fp16(W) so self-inhibition cancels against the chain.

static constexpr int NROWS  = 8192;
static constexpr int DMODEL = 1024;
static constexpr int DLCA   = 4096;
static constexpr float LAMBDA = 0.1f;
static constexpr float BETA   = 0.1f;
static constexpr float ONE_MB = 0.9f;

// ---------------------------------------------------------------- scratch
__device__ float g_b [(size_t)NROWS * DLCA];
__device__ float g_u [(size_t)NROWS * DLCA];
__device__ __half g_ahi[(size_t)NROWS * DLCA];
__device__ __half g_alo[(size_t)NROWS * DLCA];
__device__ __half g_t1hi[(size_t)NROWS * DMODEL];
__device__ __half g_xhi[(size_t)NROWS * DMODEL];
__device__ __half g_xlo[(size_t)NROWS * DMODEL];
__device__ __half g_Whi[(size_t)DMODEL * DLCA];   // [d, n] row-major
__device__ __half g_Wlo[(size_t)DMODEL * DLCA];
__device__ __half g_Wthi[(size_t)DLCA * DMODEL];  // [n, d] row-major
__device__ __half g_Wtlo[(size_t)DLCA * DMODEL];
__device__ float g_diagG[DLCA];

// ---------------------------------------------------------------- asm helpers
__device__ __forceinline__ uint32_t smem_u32(const void* p) {
    uint32_t a;
    asm("{ .reg .u64 t; cvta.to.shared.u64 t, %1; cvt.u32.u64 %0, t; }" : "=r"(a) : "l"(p));
    return a;
}
__device__ __forceinline__ void cp16(uint32_t dst, const void* src) {
    asm volatile("cp.async.cg.shared.global [%0], [%1], 16;" :: "r"(dst), "l"(src));
}
__device__ __forceinline__ void cp_commit() {
    asm volatile("cp.async.commit_group;" ::: "memory");
}
template <int N>
__device__ __forceinline__ void cp_wait() {
    asm volatile("cp.async.wait_group %0;" :: "n"(N) : "memory");
}
__device__ __forceinline__ void ldsm4(uint32_t* r, uint32_t addr) {
    asm volatile("ldmatrix.sync.aligned.m8n8.x4.shared.b16 {%0,%1,%2,%3}, [%4];"
                 : "=r"(r[0]), "=r"(r[1]), "=r"(r[2]), "=r"(r[3]) : "r"(addr));
}
__device__ __forceinline__ void mma_f16(float* c, const uint32_t* a,
                                        uint32_t b0, uint32_t b1) {
    asm volatile(
        "mma.sync.aligned.m16n8k16.row.col.f32.f16.f16.f32 "
        "{%0,%1,%2,%3}, {%4,%5,%6,%7}, {%8,%9}, {%0,%1,%2,%3};"
        : "+f"(c[0]), "+f"(c[1]), "+f"(c[2]), "+f"(c[3])
        : "r"(a[0]), "r"(a[1]), "r"(a[2]), "r"(a[3]), "r"(b0), "r"(b1));
}

// ---------------------------------------------------------------- prep kernels
__global__ void zero_diag_kernel() {
    int i = blockIdx.x * blockDim.x + threadIdx.x;
    if (i < DLCA) g_diagG[i] = 0.f;
}
__global__ void diag_kernel() {
    int n  = blockIdx.x * 512 + threadIdx.x;
    int d0 = blockIdx.y * 128;
    float s = 0.f;
    #pragma unroll 8
    for (int d = d0; d < d0 + 128; ++d) {
        float w = __half2float(g_Whi[(size_t)d * DLCA + n]);
        s = fmaf(w, w, s);
    }
    atomicAdd(&g_diagG[n], s);
}

__global__ void split_kernel(const float* __restrict__ src,
                             __half* __restrict__ hi, __half* __restrict__ lo) {
    size_t i = ((size_t)blockIdx.x * blockDim.x + threadIdx.x) * 4;
    float4 v = *reinterpret_cast<const float4*>(src + i);
    float vv[4] = {v.x, v.y, v.z, v.w};
    __half2 hp[2], lp[2];
    #pragma unroll
    for (int j = 0; j < 2; ++j) {
        __half h0 = __float2half_rn(vv[2*j]);
        __half h1 = __float2half_rn(vv[2*j+1]);
        hp[j] = __halves2half2(h0, h1);
        lp[j] = __halves2half2(__float2half_rn(vv[2*j]   - __half2float(h0)),
                               __float2half_rn(vv[2*j+1] - __half2float(h1)));
    }
    *reinterpret_cast<uint2*>(hi + i) = *reinterpret_cast<const uint2*>(hp);
    *reinterpret_cast<uint2*>(lo + i) = *reinterpret_cast<const uint2*>(lp);
}

__global__ void transpose_split_kernel(const float* __restrict__ W) {
    __shared__ float tile[32][33];
    int bx = blockIdx.x * 32;   // n
    int by = blockIdx.y * 32;   // d
    for (int i = threadIdx.y; i < 32; i += 8)
        tile[i][threadIdx.x] = W[(size_t)(by + i) * DLCA + bx + threadIdx.x];
    __syncthreads();
    for (int i = threadIdx.y; i < 32; i += 8) {
        int n = bx + i;
        int d = by + threadIdx.x;
        float v = tile[threadIdx.x][i];
        __half h = __float2half_rn(v);
        g_Wthi[(size_t)n * DMODEL + d] = h;
        g_Wtlo[(size_t)n * DMODEL + d] = __float2half_rn(v - __half2float(h));
    }
}

// ---------------------------------------------------------------- main GEMM
// C tile 128(M) x 256(N); A row-major [M,K], B row-major [N,K] (TN).
// BK=32 fp16, SMEM rows padded to 80B. 16 warps as 4(M)x4(N), warp 32x64.
// 3-stage cp.async pipeline. AT/BT = number of fp16 terms per operand.
static constexpr int ROWB   = 80;
static constexpr int A_TILE = 128 * ROWB;    // 10240
static constexpr int B_TILE = 256 * ROWB;    // 20480

template <int AT, int BT>
__device__ __forceinline__ void stage_load(uint32_t sb,
        const __half* __restrict__ Ah, const __half* __restrict__ Al,
        const __half* __restrict__ Bh, const __half* __restrict__ Bl,
        int rowBase, int colBase, int k0, int K, int tid) {
    {
        int r = tid >> 2, cc = tid & 3;
        uint32_t off = (uint32_t)(r * ROWB + cc * 16);
        size_t ga = (size_t)(rowBase + r) * K + k0 + cc * 8;
        cp16(sb + off, Ah + ga);
        if (AT == 2) cp16(sb + A_TILE + off, Al + ga);
    }
    #pragma unroll
    for (int i = 0; i < 2; ++i) {
        int idx = tid + i * 512;
        int r = idx >> 2, cc = idx & 3;
        uint32_t off = (uint32_t)(r * ROWB + cc * 16);
        size_t gb = (size_t)(colBase + r) * K + k0 + cc * 8;
        cp16(sb + AT * A_TILE + off, Bh + gb);
        if (BT == 2) cp16(sb + AT * A_TILE + B_TILE + off, Bl + gb);
    }
}

// EPI: 0 = b-init, 1 = t1 (hi only), 2 = LCA update, 3 = out fp32
template <int EPI, int AT, int BT, bool WLO>
__global__ void __launch_bounds__(512, 1)
lca_gemm(const __half* __restrict__ Ah, const __half* __restrict__ Al,
         const __half* __restrict__ Bh, const __half* __restrict__ Bl,
         int K, float* __restrict__ outp) {
    constexpr int STAGE_BYTES = AT * A_TILE + BT * B_TILE;
    extern __shared__ __align__(256) char smem[];
    const uint32_t sbase = smem_u32(smem);
    const int tid = threadIdx.x;
    const int wid = tid >> 5;
    const int lid = tid & 31;
    const int warpM = wid >> 2;          // 0..3  (m offset 32)
    const int warpN = wid & 3;           // 0..3  (n offset 64)
    const int rowBase = blockIdx.y * 128;
    const int colBase = blockIdx.x * 256;
    const int KT = K >> 5;

    float acc[2][8][4];
    #pragma unroll
    for (int mi = 0; mi < 2; ++mi)
        #pragma unroll
        for (int ni = 0; ni < 8; ++ni)
            #pragma unroll
            for (int q = 0; q < 4; ++q) acc[mi][ni][q] = 0.f;

    stage_load<AT, BT>(sbase, Ah, Al, Bh, Bl, rowBase, colBase, 0, K, tid);
    cp_commit();
    stage_load<AT, BT>(sbase + STAGE_BYTES, Ah, Al, Bh, Bl, rowBase, colBase, 32, K, tid);
    cp_commit();

    const uint32_t lrow = (uint32_t)(lid & 15);
    const uint32_t lcol = (uint32_t)((lid >> 4) * 16);

    int sidx = 0;
    for (int kt = 0; kt < KT; ++kt) {
        cp_wait<1>();
        __syncthreads();

        if (kt + 2 < KT)
            stage_load<AT, BT>(sbase + ((sidx + 2) % 3) * STAGE_BYTES,
                               Ah, Al, Bh, Bl, rowBase, colBase, (kt + 2) * 32, K, tid);
        cp_commit();

        const uint32_t sb = sbase + sidx * STAGE_BYTES;
        const uint32_t aBase = sb + (uint32_t)(warpM * 32) * ROWB;
        const uint32_t bBase = sb + AT * A_TILE + (uint32_t)(warpN * 64) * ROWB;

        #pragma unroll
        for (int ks = 0; ks < 2; ++ks) {
            const uint32_t kb = (uint32_t)(ks * 32) + lcol;
            uint32_t ah[2][4], al[2][4], bf[4][4];
            #pragma unroll
            for (int mi = 0; mi < 2; ++mi) {
                uint32_t ad = aBase + (uint32_t)(mi * 16 + lrow) * ROWB + kb;
                ldsm4(ah[mi], ad);
                if (AT == 2) ldsm4(al[mi], ad + A_TILE);
            }
            #pragma unroll
            for (int nj = 0; nj < 4; ++nj)
                ldsm4(bf[nj], bBase + (uint32_t)(nj * 16 + lrow) * ROWB + kb);

            #pragma unroll
            for (int mi = 0; mi < 2; ++mi)
                #pragma unroll
                for (int ni = 0; ni < 8; ++ni) {
                    const int nj = ni >> 1, nr = ni & 1;
                    mma_f16(acc[mi][ni], ah[mi], bf[nj][nr], bf[nj][nr + 2]);
                    if (AT == 2)
                        mma_f16(acc[mi][ni], al[mi], bf[nj][nr], bf[nj][nr + 2]);
                }
            if (BT == 2) {
                #pragma unroll
                for (int nj = 0; nj < 4; ++nj)
                    ldsm4(bf[nj], bBase + B_TILE + (uint32_t)(nj * 16 + lrow) * ROWB + kb);
                #pragma unroll
                for (int mi = 0; mi < 2; ++mi)
                    #pragma unroll
                    for (int ni = 0; ni < 8; ++ni) {
                        const int nj = ni >> 1, nr = ni & 1;
                        mma_f16(acc[mi][ni], ah[mi], bf[nj][nr], bf[nj][nr + 2]);
                    }
            }
        }
        __syncthreads();
        sidx = (sidx + 1) % 3;
    }

    // ------------------------------------------------------------ epilogue
    const int qrow = lid >> 2;
    const int qcol = (lid & 3) * 2;
    const int ldo = (EPI == 1 || EPI == 3) ? DMODEL : DLCA;

    #pragma unroll
    for (int mi = 0; mi < 2; ++mi) {
        #pragma unroll
        for (int ni = 0; ni < 8; ++ni) {
            const int r0 = rowBase + warpM * 32 + mi * 16 + qrow;
            const int c  = colBase + warpN * 64 + ni * 8 + qcol;
            #pragma unroll
            for (int h = 0; h < 2; ++h) {
                const int r = r0 + h * 8;
                const size_t base = (size_t)r * ldo + c;
                const float v0 = acc[mi][ni][2*h], v1 = acc[mi][ni][2*h + 1];
                if (EPI == 0) {
                    float u0 = BETA * v0, u1 = BETA * v1;
                    *reinterpret_cast<float2*>(g_b + base) = make_float2(v0, v1);
                    *reinterpret_cast<float2*>(g_u + base) = make_float2(u0, u1);
                    float a0 = fmaxf(u0 - LAMBDA, 0.f), a1 = fmaxf(u1 - LAMBDA, 0.f);
                    *reinterpret_cast<__half2*>(g_ahi + base) =
                        __halves2half2(__float2half_rn(a0), __float2half_rn(a1));
                } else if (EPI == 2) {
                    float2 uo = *reinterpret_cast<const float2*>(g_u + base);
                    float2 bv = *reinterpret_cast<const float2*>(g_b + base);
                    float2 dg = *reinterpret_cast<const float2*>(g_diagG + c);
                    float ao0 = fmaxf(uo.x - LAMBDA, 0.f), ao1 = fmaxf(uo.y - LAMBDA, 0.f);
                    float u0 = ONE_MB * uo.x + BETA * (bv.x - v0 + ao0 * dg.x);
                    float u1 = ONE_MB * uo.y + BETA * (bv.y - v1 + ao1 * dg.y);
                    *reinterpret_cast<float2*>(g_u + base) = make_float2(u0, u1);
                    float a0 = fmaxf(u0 - LAMBDA, 0.f), a1 = fmaxf(u1 - LAMBDA, 0.f);
                    __half h0 = __float2half_rn(a0), h1 = __float2half_rn(a1);
                    *reinterpret_cast<__half2*>(g_ahi + base) = __halves2half2(h0, h1);
                    if (WLO)
                        *reinterpret_cast<__half2*>(g_alo + base) =
                            __halves2half2(__float2half_rn(a0 - __half2float(h0)),
                                           __float2half_rn(a1 - __half2float(h1)));
                } else if (EPI == 1) {
                    *reinterpret_cast<__half2*>(g_t1hi + base) =
                        __halves2half2(__float2half_rn(v0), __float2half_rn(v1));
                } else {
                    *reinterpret_cast<float2*>(outp + base) = make_float2(v0, v1);
                }
            }
        }
    }
}

// ---------------------------------------------------------------- launch
extern "C" void kernel_launch(void* const* d_in, const int* in_sizes, int n_in,
                              void* d_out, int out_size) {
    const float* x = (const float*)d_in[0];   // [8192, 1024]
    const float* W = (const float*)d_in[1];   // [1024, 4096]
    float* out = (float*)d_out;               // [8192, 1024]

    __half *xhi, *xlo, *Whi, *Wlo, *Wthi, *Wtlo, *ahi, *alo, *t1hi;
    cudaGetSymbolAddress((void**)&xhi,  g_xhi);
    cudaGetSymbolAddress((void**)&xlo,  g_xlo);
    cudaGetSymbolAddress((void**)&Whi,  g_Whi);
    cudaGetSymbolAddress((void**)&Wlo,  g_Wlo);
    cudaGetSymbolAddress((void**)&Wthi, g_Wthi);
    cudaGetSymbolAddress((void**)&Wtlo, g_Wtlo);
    cudaGetSymbolAddress((void**)&ahi,  g_ahi);
    cudaGetSymbolAddress((void**)&alo,  g_alo);
    cudaGetSymbolAddress((void**)&t1hi, g_t1hi);

    constexpr int SM11 = 3 * (A_TILE + B_TILE);          //  92160
    constexpr int SM22 = 3 * (2 * A_TILE + 2 * B_TILE);  // 184320
    cudaFuncSetAttribute((const void*)lca_gemm<0,2,2,false>, cudaFuncAttributeMaxDynamicSharedMemorySize, SM22);
    cudaFuncSetAttribute((const void*)lca_gemm<1,1,1,false>, cudaFuncAttributeMaxDynamicSharedMemorySize, SM11);
    cudaFuncSetAttribute((const void*)lca_gemm<2,1,1,false>, cudaFuncAttributeMaxDynamicSharedMemorySize, SM11);
    cudaFuncSetAttribute((const void*)lca_gemm<2,1,1,true>,  cudaFuncAttributeMaxDynamicSharedMemorySize, SM11);
    cudaFuncSetAttribute((const void*)lca_gemm<3,2,2,false>, cudaFuncAttributeMaxDynamicSharedMemorySize, SM22);

    // prep
    split_kernel<<<(int)(((size_t)NROWS * DMODEL) / 1024), 256>>>(x, xhi, xlo);
    split_kernel<<<(int)(((size_t)DMODEL * DLCA) / 1024), 256>>>(W, Whi, Wlo);
    transpose_split_kernel<<<dim3(DLCA / 32, DMODEL / 32), dim3(32, 8)>>>(W);
    zero_diag_kernel<<<DLCA / 256, 256>>>();
    diag_kernel<<<dim3(DLCA / 512, 8), 512>>>();

    // b = x@W (3-term) ; u = 0.1b ; a = fp16(relu(u - lambda))
    lca_gemm<0,2,2,false><<<dim3(DLCA / 256, NROWS / 128), 512, SM22>>>(
        xhi, xlo, Wthi, Wtlo, DMODEL, nullptr);

    for (int it = 0; it < 9; ++it) {
        // t1 = a @ W^T (1 MMA/product)
        lca_gemm<1,1,1,false><<<dim3(DMODEL / 256, NROWS / 128), 512, SM11>>>(
            ahi, nullptr, Whi, nullptr, DLCA, nullptr);
        // u = 0.9u + 0.1(b - t1@W + a*diagG) ; a split on final iteration
        if (it < 8)
            lca_gemm<2,1,1,false><<<dim3(DLCA / 256, NROWS / 128), 512, SM11>>>(
                t1hi, nullptr, Wthi, nullptr, DMODEL, nullptr);
        else
            lca_gemm<2,1,1,true><<<dim3(DLCA / 256, NROWS / 128), 512, SM11>>>(
                t1hi, nullptr, Wthi, nullptr, DMODEL, nullptr);
    }

    // out = a @ W^T (3-term, fp32)
    lca_gemm<3,2,2,false><<<dim3(DMODEL / 256, NROWS / 128), 512, SM22>>>(
        ahi, alo, Whi, Wlo, DLCA, out);
}

// round 8
// speedup vs baseline: 5.2202x; 1.1167x over previous
#include <cuda_runtime.h>
#include <cuda_fp16.h>
#include <cstdint>

// LCA layer via mma.sync fp16 split-GEMMs, all against W~ = fp16(W):
//   b = x@W~ (x 2-term) ;  u1 = 0.1*b
//   9x: a = relu(u-0.1); t1 = a@W~^T; u = 0.9u + 0.1*(b - t1@W~ + a*diagG~)
//   out = relu(u-0.1) @ W~^T  (a 2-term)
// diagG~ from fp16(W) so self-inhibition cancels exactly against the chain.
// BK=64 K-tiles (144B smem row pitch, conflict-free), 3-stage cp.async.

static constexpr int NROWS  = 8192;
static constexpr int DMODEL = 1024;
static constexpr int DLCA   = 4096;
static constexpr float LAMBDA = 0.1f;
static constexpr float BETA   = 0.1f;
static constexpr float ONE_MB = 0.9f;

// ---------------------------------------------------------------- scratch
__device__ float g_b [(size_t)NROWS * DLCA];
__device__ float g_u [(size_t)NROWS * DLCA];
__device__ __half g_ahi[(size_t)NROWS * DLCA];
__device__ __half g_alo[(size_t)NROWS * DLCA];
__device__ __half g_t1hi[(size_t)NROWS * DMODEL];
__device__ __half g_xhi[(size_t)NROWS * DMODEL];
__device__ __half g_xlo[(size_t)NROWS * DMODEL];
__device__ __half g_Whi[(size_t)DMODEL * DLCA];   // [d, n] row-major
__device__ __half g_Wthi[(size_t)DLCA * DMODEL];  // [n, d] row-major
__device__ float g_diagG[DLCA];

// ---------------------------------------------------------------- asm helpers
__device__ __forceinline__ uint32_t smem_u32(const void* p) {
    uint32_t a;
    asm("{ .reg .u64 t; cvta.to.shared.u64 t, %1; cvt.u32.u64 %0, t; }" : "=r"(a) : "l"(p));
    return a;
}
__device__ __forceinline__ void cp16(uint32_t dst, const void* src) {
    asm volatile("cp.async.cg.shared.global [%0], [%1], 16;" :: "r"(dst), "l"(src));
}
__device__ __forceinline__ void cp_commit() {
    asm volatile("cp.async.commit_group;" ::: "memory");
}
template <int N>
__device__ __forceinline__ void cp_wait() {
    asm volatile("cp.async.wait_group %0;" :: "n"(N) : "memory");
}
__device__ __forceinline__ void ldsm4(uint32_t* r, uint32_t addr) {
    asm volatile("ldmatrix.sync.aligned.m8n8.x4.shared.b16 {%0,%1,%2,%3}, [%4];"
                 : "=r"(r[0]), "=r"(r[1]), "=r"(r[2]), "=r"(r[3]) : "r"(addr));
}
__device__ __forceinline__ void mma_f16(float* c, const uint32_t* a,
                                        uint32_t b0, uint32_t b1) {
    asm volatile(
        "mma.sync.aligned.m16n8k16.row.col.f32.f16.f16.f32 "
        "{%0,%1,%2,%3}, {%4,%5,%6,%7}, {%8,%9}, {%0,%1,%2,%3};"
        : "+f"(c[0]), "+f"(c[1]), "+f"(c[2]), "+f"(c[3])
        : "r"(a[0]), "r"(a[1]), "r"(a[2]), "r"(a[3]), "r"(b0), "r"(b1));
}

// ---------------------------------------------------------------- prep kernels
__global__ void zero_diag_kernel() {
    int i = blockIdx.x * blockDim.x + threadIdx.x;
    if (i < DLCA) g_diagG[i] = 0.f;
}
// diagG[n] = sum_d fp16(W)[d,n]^2 (16 d-chunks of 64, atomicAdd)
__global__ void diag_kernel() {
    int n  = blockIdx.x * 512 + threadIdx.x;
    int d0 = blockIdx.y * 64;
    float s = 0.f;
    #pragma unroll 8
    for (int d = d0; d < d0 + 64; ++d) {
        float w = __half2float(g_Whi[(size_t)d * DLCA + n]);
        s = fmaf(w, w, s);
    }
    atomicAdd(&g_diagG[n], s);
}

// split src -> hi (+ optional lo)
template <bool LO>
__global__ void split_kernel(const float* __restrict__ src,
                             __half* __restrict__ hi, __half* __restrict__ lo) {
    size_t i = ((size_t)blockIdx.x * blockDim.x + threadIdx.x) * 4;
    float4 v = *reinterpret_cast<const float4*>(src + i);
    float vv[4] = {v.x, v.y, v.z, v.w};
    __half2 hp[2], lp[2];
    #pragma unroll
    for (int j = 0; j < 2; ++j) {
        __half h0 = __float2half_rn(vv[2*j]);
        __half h1 = __float2half_rn(vv[2*j+1]);
        hp[j] = __halves2half2(h0, h1);
        if (LO)
            lp[j] = __halves2half2(__float2half_rn(vv[2*j]   - __half2float(h0)),
                                   __float2half_rn(vv[2*j+1] - __half2float(h1)));
    }
    *reinterpret_cast<uint2*>(hi + i) = *reinterpret_cast<const uint2*>(hp);
    if (LO) *reinterpret_cast<uint2*>(lo + i) = *reinterpret_cast<const uint2*>(lp);
}

__global__ void transpose_kernel(const float* __restrict__ W) {
    __shared__ float tile[32][33];
    int bx = blockIdx.x * 32;   // n
    int by = blockIdx.y * 32;   // d
    for (int i = threadIdx.y; i < 32; i += 8)
        tile[i][threadIdx.x] = W[(size_t)(by + i) * DLCA + bx + threadIdx.x];
    __syncthreads();
    for (int i = threadIdx.y; i < 32; i += 8) {
        int n = bx + i;
        int d = by + threadIdx.x;
        g_Wthi[(size_t)n * DMODEL + d] = __float2half_rn(tile[threadIdx.x][i]);
    }
}

// ---------------------------------------------------------------- main GEMM
// C tile 128(M) x 256(N); A row-major [M,K] (AT terms), B row-major [N,K]
// (single fp16 term). BK=64, smem row pitch 144B (conflict-free ldmatrix).
// 16 warps as 4(M)x4(N); warp tile 32x64. 3-stage cp.async pipeline.
static constexpr int ROWB   = 144;           // 64 fp16 = 128B data + 16B pad
static constexpr int A_TILE = 128 * ROWB;    // 18432
static constexpr int B_TILE = 256 * ROWB;    // 36864

template <int AT>
__device__ __forceinline__ void stage_load(uint32_t sb,
        const __half* __restrict__ Ah, const __half* __restrict__ Al,
        const __half* __restrict__ Bh,
        int rowBase, int colBase, int k0, int K, int tid) {
    #pragma unroll
    for (int i = 0; i < 2; ++i) {
        int idx = tid + i * 512;            // 1024 chunks: 128 rows x 8
        int r = idx >> 3, cc = idx & 7;
        uint32_t off = (uint32_t)(r * ROWB + cc * 16);
        size_t ga = (size_t)(rowBase + r) * K + k0 + cc * 8;
        cp16(sb + off, Ah + ga);
        if (AT == 2) cp16(sb + A_TILE + off, Al + ga);
    }
    #pragma unroll
    for (int i = 0; i < 4; ++i) {
        int idx = tid + i * 512;            // 2048 chunks: 256 rows x 8
        int r = idx >> 3, cc = idx & 7;
        uint32_t off = (uint32_t)(r * ROWB + cc * 16);
        size_t gb = (size_t)(colBase + r) * K + k0 + cc * 8;
        cp16(sb + AT * A_TILE + off, Bh + gb);
    }
}

// EPI: 0 = b-init, 1 = t1 (hi only), 2 = LCA update, 3 = out fp32
template <int EPI, int AT, bool WLO>
__global__ void __launch_bounds__(512, 1)
lca_gemm(const __half* __restrict__ Ah, const __half* __restrict__ Al,
         const __half* __restrict__ Bh,
         int K, float* __restrict__ outp) {
    constexpr int STAGE_BYTES = AT * A_TILE + B_TILE;
    extern __shared__ __align__(256) char smem[];
    const uint32_t sbase = smem_u32(smem);
    const int tid = threadIdx.x;
    const int wid = tid >> 5;
    const int lid = tid & 31;
    const int warpM = wid >> 2;          // 0..3  (m offset 32)
    const int warpN = wid & 3;           // 0..3  (n offset 64)
    const int rowBase = blockIdx.y * 128;
    const int colBase = blockIdx.x * 256;
    const int KT = K >> 6;

    float acc[2][8][4];
    #pragma unroll
    for (int mi = 0; mi < 2; ++mi)
        #pragma unroll
        for (int ni = 0; ni < 8; ++ni)
            #pragma unroll
            for (int q = 0; q < 4; ++q) acc[mi][ni][q] = 0.f;

    stage_load<AT>(sbase, Ah, Al, Bh, rowBase, colBase, 0, K, tid);
    cp_commit();
    stage_load<AT>(sbase + STAGE_BYTES, Ah, Al, Bh, rowBase, colBase, 64, K, tid);
    cp_commit();

    const uint32_t lrow = (uint32_t)(lid & 15);
    const uint32_t lcol = (uint32_t)((lid >> 4) * 16);

    int sidx = 0;
    for (int kt = 0; kt < KT; ++kt) {
        cp_wait<1>();
        __syncthreads();

        if (kt + 2 < KT)
            stage_load<AT>(sbase + ((sidx + 2) % 3) * STAGE_BYTES,
                           Ah, Al, Bh, rowBase, colBase, (kt + 2) * 64, K, tid);
        cp_commit();

        const uint32_t sb = sbase + sidx * STAGE_BYTES;
        const uint32_t aBase = sb + (uint32_t)(warpM * 32) * ROWB;
        const uint32_t bBase = sb + AT * A_TILE + (uint32_t)(warpN * 64) * ROWB;

        #pragma unroll
        for (int ks = 0; ks < 4; ++ks) {
            const uint32_t kb = (uint32_t)(ks * 32) + lcol;
            uint32_t ah[2][4], al[2][4], bf[4][4];
            #pragma unroll
            for (int mi = 0; mi < 2; ++mi) {
                uint32_t ad = aBase + (uint32_t)(mi * 16 + lrow) * ROWB + kb;
                ldsm4(ah[mi], ad);
                if (AT == 2) ldsm4(al[mi], ad + A_TILE);
            }
            #pragma unroll
            for (int nj = 0; nj < 4; ++nj)
                ldsm4(bf[nj], bBase + (uint32_t)(nj * 16 + lrow) * ROWB + kb);

            #pragma unroll
            for (int mi = 0; mi < 2; ++mi)
                #pragma unroll
                for (int ni = 0; ni < 8; ++ni) {
                    const int nj = ni >> 1, nr = ni & 1;
                    mma_f16(acc[mi][ni], ah[mi], bf[nj][nr], bf[nj][nr + 2]);
                    if (AT == 2)
                        mma_f16(acc[mi][ni], al[mi], bf[nj][nr], bf[nj][nr + 2]);
                }
        }
        __syncthreads();
        sidx = (sidx + 1) % 3;
    }

    // ------------------------------------------------------------ epilogue
    const int qrow = lid >> 2;
    const int qcol = (lid & 3) * 2;
    const int ldo = (EPI == 1 || EPI == 3) ? DMODEL : DLCA;

    #pragma unroll
    for (int mi = 0; mi < 2; ++mi) {
        #pragma unroll
        for (int ni = 0; ni < 8; ++ni) {
            const int r0 = rowBase + warpM * 32 + mi * 16 + qrow;
            const int c  = colBase + warpN * 64 + ni * 8 + qcol;
            #pragma unroll
            for (int h = 0; h < 2; ++h) {
                const int r = r0 + h * 8;
                const size_t base = (size_t)r * ldo + c;
                const float v0 = acc[mi][ni][2*h], v1 = acc[mi][ni][2*h + 1];
                if (EPI == 0) {
                    float u0 = BETA * v0, u1 = BETA * v1;
                    *reinterpret_cast<float2*>(g_b + base) = make_float2(v0, v1);
                    *reinterpret_cast<float2*>(g_u + base) = make_float2(u0, u1);
                    float a0 = fmaxf(u0 - LAMBDA, 0.f), a1 = fmaxf(u1 - LAMBDA, 0.f);
                    *reinterpret_cast<__half2*>(g_ahi + base) =
                        __halves2half2(__float2half_rn(a0), __float2half_rn(a1));
                } else if (EPI == 2) {
                    float2 uo = *reinterpret_cast<const float2*>(g_u + base);
                    float2 bv = *reinterpret_cast<const float2*>(g_b + base);
                    float2 dg = *reinterpret_cast<const float2*>(g_diagG + c);
                    float ao0 = fmaxf(uo.x - LAMBDA, 0.f), ao1 = fmaxf(uo.y - LAMBDA, 0.f);
                    float u0 = ONE_MB * uo.x + BETA * (bv.x - v0 + ao0 * dg.x);
                    float u1 = ONE_MB * uo.y + BETA * (bv.y - v1 + ao1 * dg.y);
                    *reinterpret_cast<float2*>(g_u + base) = make_float2(u0, u1);
                    float a0 = fmaxf(u0 - LAMBDA, 0.f), a1 = fmaxf(u1 - LAMBDA, 0.f);
                    __half h0 = __float2half_rn(a0), h1 = __float2half_rn(a1);
                    *reinterpret_cast<__half2*>(g_ahi + base) = __halves2half2(h0, h1);
                    if (WLO)
                        *reinterpret_cast<__half2*>(g_alo + base) =
                            __halves2half2(__float2half_rn(a0 - __half2float(h0)),
                                           __float2half_rn(a1 - __half2float(h1)));
                } else if (EPI == 1) {
                    *reinterpret_cast<__half2*>(g_t1hi + base) =
                        __halves2half2(__float2half_rn(v0), __float2half_rn(v1));
                } else {
                    *reinterpret_cast<float2*>(outp + base) = make_float2(v0, v1);
                }
            }
        }
    }
}

// ---------------------------------------------------------------- launch
extern "C" void kernel_launch(void* const* d_in, const int* in_sizes, int n_in,
                              void* d_out, int out_size) {
    const float* x = (const float*)d_in[0];   // [8192, 1024]
    const float* W = (const float*)d_in[1];   // [1024, 4096]
    float* out = (float*)d_out;               // [8192, 1024]

    __half *xhi, *xlo, *Whi, *Wthi, *ahi, *alo, *t1hi;
    cudaGetSymbolAddress((void**)&xhi,  g_xhi);
    cudaGetSymbolAddress((void**)&xlo,  g_xlo);
    cudaGetSymbolAddress((void**)&Whi,  g_Whi);
    cudaGetSymbolAddress((void**)&Wthi, g_Wthi);
    cudaGetSymbolAddress((void**)&ahi,  g_ahi);
    cudaGetSymbolAddress((void**)&alo,  g_alo);
    cudaGetSymbolAddress((void**)&t1hi, g_t1hi);

    constexpr int SM1 = 3 * (A_TILE + B_TILE);       // 165888
    constexpr int SM2 = 3 * (2 * A_TILE + B_TILE);   // 221184
    cudaFuncSetAttribute((const void*)lca_gemm<0,2,false>, cudaFuncAttributeMaxDynamicSharedMemorySize, SM2);
    cudaFuncSetAttribute((const void*)lca_gemm<1,1,false>, cudaFuncAttributeMaxDynamicSharedMemorySize, SM1);
    cudaFuncSetAttribute((const void*)lca_gemm<2,1,false>, cudaFuncAttributeMaxDynamicSharedMemorySize, SM1);
    cudaFuncSetAttribute((const void*)lca_gemm<2,1,true>,  cudaFuncAttributeMaxDynamicSharedMemorySize, SM1);
    cudaFuncSetAttribute((const void*)lca_gemm<3,2,false>, cudaFuncAttributeMaxDynamicSharedMemorySize, SM2);

    // prep
    split_kernel<true><<<(int)(((size_t)NROWS * DMODEL) / 1024), 256>>>(x, xhi, xlo);
    split_kernel<false><<<(int)(((size_t)DMODEL * DLCA) / 1024), 256>>>(W, Whi, nullptr);
    transpose_kernel<<<dim3(DLCA / 32, DMODEL / 32), dim3(32, 8)>>>(W);
    zero_diag_kernel<<<DLCA / 256, 256>>>();
    diag_kernel<<<dim3(DLCA / 512, 16), 512>>>();

    // b = x@W~ (x 2-term) ; u = 0.1b ; a = fp16(relu(u - lambda))
    lca_gemm<0,2,false><<<dim3(DLCA / 256, NROWS / 128), 512, SM2>>>(
        xhi, xlo, Wthi, DMODEL, nullptr);

    for (int it = 0; it < 9; ++it) {
        // t1 = a @ W~^T (1 MMA/product)
        lca_gemm<1,1,false><<<dim3(DMODEL / 256, NROWS / 128), 512, SM1>>>(
            ahi, nullptr, Whi, DLCA, nullptr);
        // u = 0.9u + 0.1(b - t1@W~ + a*diagG~) ; a split on final iteration
        if (it < 8)
            lca_gemm<2,1,false><<<dim3(DLCA / 256, NROWS / 128), 512, SM1>>>(
                t1hi, nullptr, Wthi, DMODEL, nullptr);
        else
            lca_gemm<2,1,true><<<dim3(DLCA / 256, NROWS / 128), 512, SM1>>>(
                t1hi, nullptr, Wthi, DMODEL, nullptr);
    }

    // out = a @ W~^T (a 2-term, fp32 out)
    lca_gemm<3,2,false><<<dim3(DMODEL / 256, NROWS / 128), 512, SM2>>>(
        ahi, alo, Whi, DLCA, out);
}

// round 9
// speedup vs baseline: 5.6322x; 1.0789x over previous
#include <cuda_runtime.h>
#include <cuda_fp16.h>
#include <cstdint>

// LCA layer via mma.sync fp16 GEMMs, entirely against W~ = fp16(W):
//   b = fp16(x)@W~ ;  u1 = 0.1*b
//   9x: a = relu(u-0.1); t1 = a@W~^T; u = 0.9u + 0.1*(b - t1@W~ + a*diagG~)
//   out = fp16(relu(u-0.1)) @ W~^T
// Single fp16 term per operand everywhere (20 GEMM-units total); fp16
// rounding of x/a/t1 are ~2^-12 random perturbations, total out err ~2.6e-4.
// diagG~ from fp16(W) so self-inhibition cancels exactly against the chain.
// BK=64 K-tiles (144B smem row pitch, conflict-free), 3-stage cp.async.

static constexpr int NROWS  = 8192;
static constexpr int DMODEL = 1024;
static constexpr int DLCA   = 4096;
static constexpr float LAMBDA = 0.1f;
static constexpr float BETA   = 0.1f;
static constexpr float ONE_MB = 0.9f;

// ---------------------------------------------------------------- scratch
__device__ float g_b [(size_t)NROWS * DLCA];
__device__ float g_u [(size_t)NROWS * DLCA];
__device__ __half g_ahi[(size_t)NROWS * DLCA];
__device__ __half g_t1hi[(size_t)NROWS * DMODEL];
__device__ __half g_xhi[(size_t)NROWS * DMODEL];
__device__ __half g_Whi[(size_t)DMODEL * DLCA];   // [d, n] row-major
__device__ __half g_Wthi[(size_t)DLCA * DMODEL];  // [n, d] row-major
__device__ float g_diagG[DLCA];

// ---------------------------------------------------------------- asm helpers
__device__ __forceinline__ uint32_t smem_u32(const void* p) {
    uint32_t a;
    asm("{ .reg .u64 t; cvta.to.shared.u64 t, %1; cvt.u32.u64 %0, t; }" : "=r"(a) : "l"(p));
    return a;
}
__device__ __forceinline__ void cp16(uint32_t dst, const void* src) {
    asm volatile("cp.async.cg.shared.global [%0], [%1], 16;" :: "r"(dst), "l"(src));
}
__device__ __forceinline__ void cp_commit() {
    asm volatile("cp.async.commit_group;" ::: "memory");
}
template <int N>
__device__ __forceinline__ void cp_wait() {
    asm volatile("cp.async.wait_group %0;" :: "n"(N) : "memory");
}
__device__ __forceinline__ void ldsm4(uint32_t* r, uint32_t addr) {
    asm volatile("ldmatrix.sync.aligned.m8n8.x4.shared.b16 {%0,%1,%2,%3}, [%4];"
                 : "=r"(r[0]), "=r"(r[1]), "=r"(r[2]), "=r"(r[3]) : "r"(addr));
}
__device__ __forceinline__ void mma_f16(float* c, const uint32_t* a,
                                        uint32_t b0, uint32_t b1) {
    asm volatile(
        "mma.sync.aligned.m16n8k16.row.col.f32.f16.f16.f32 "
        "{%0,%1,%2,%3}, {%4,%5,%6,%7}, {%8,%9}, {%0,%1,%2,%3};"
        : "+f"(c[0]), "+f"(c[1]), "+f"(c[2]), "+f"(c[3])
        : "r"(a[0]), "r"(a[1]), "r"(a[2]), "r"(a[3]), "r"(b0), "r"(b1));
}

// ---------------------------------------------------------------- prep kernels
__global__ void zero_diag_kernel() {
    int i = blockIdx.x * blockDim.x + threadIdx.x;
    if (i < DLCA) g_diagG[i] = 0.f;
}
// diagG[n] = sum_d fp16(W)[d,n]^2 (16 d-chunks of 64, atomicAdd)
__global__ void diag_kernel() {
    int n  = blockIdx.x * 512 + threadIdx.x;
    int d0 = blockIdx.y * 64;
    float s = 0.f;
    #pragma unroll 8
    for (int d = d0; d < d0 + 64; ++d) {
        float w = __half2float(g_Whi[(size_t)d * DLCA + n]);
        s = fmaf(w, w, s);
    }
    atomicAdd(&g_diagG[n], s);
}

// fp16 truncate src -> hi
__global__ void half_kernel(const float* __restrict__ src, __half* __restrict__ hi) {
    size_t i = ((size_t)blockIdx.x * blockDim.x + threadIdx.x) * 4;
    float4 v = *reinterpret_cast<const float4*>(src + i);
    __half2 hp[2];
    hp[0] = __halves2half2(__float2half_rn(v.x), __float2half_rn(v.y));
    hp[1] = __halves2half2(__float2half_rn(v.z), __float2half_rn(v.w));
    *reinterpret_cast<uint2*>(hi + i) = *reinterpret_cast<const uint2*>(hp);
}

__global__ void transpose_kernel(const float* __restrict__ W) {
    __shared__ float tile[32][33];
    int bx = blockIdx.x * 32;   // n
    int by = blockIdx.y * 32;   // d
    for (int i = threadIdx.y; i < 32; i += 8)
        tile[i][threadIdx.x] = W[(size_t)(by + i) * DLCA + bx + threadIdx.x];
    __syncthreads();
    for (int i = threadIdx.y; i < 32; i += 8) {
        int n = bx + i;
        int d = by + threadIdx.x;
        g_Wthi[(size_t)n * DMODEL + d] = __float2half_rn(tile[threadIdx.x][i]);
    }
}

// ---------------------------------------------------------------- main GEMM
// C tile 128(M) x 256(N); A row-major [M,K], B row-major [N,K], single fp16
// term each. BK=64, smem row pitch 144B (conflict-free ldmatrix).
// 16 warps as 4(M)x4(N); warp tile 32x64. 3-stage cp.async pipeline.
static constexpr int ROWB   = 144;           // 64 fp16 = 128B data + 16B pad
static constexpr int A_TILE = 128 * ROWB;    // 18432
static constexpr int B_TILE = 256 * ROWB;    // 36864
static constexpr int STAGE_BYTES = A_TILE + B_TILE;        // 55296
static constexpr int SMEM_TOTAL  = 3 * STAGE_BYTES;        // 165888

__device__ __forceinline__ void stage_load(uint32_t sb,
        const __half* __restrict__ Ah, const __half* __restrict__ Bh,
        int rowBase, int colBase, int k0, int K, int tid) {
    #pragma unroll
    for (int i = 0; i < 2; ++i) {
        int idx = tid + i * 512;            // 1024 chunks: 128 rows x 8
        int r = idx >> 3, cc = idx & 7;
        uint32_t off = (uint32_t)(r * ROWB + cc * 16);
        cp16(sb + off, Ah + (size_t)(rowBase + r) * K + k0 + cc * 8);
    }
    #pragma unroll
    for (int i = 0; i < 4; ++i) {
        int idx = tid + i * 512;            // 2048 chunks: 256 rows x 8
        int r = idx >> 3, cc = idx & 7;
        uint32_t off = (uint32_t)(r * ROWB + cc * 16);
        cp16(sb + A_TILE + off, Bh + (size_t)(colBase + r) * K + k0 + cc * 8);
    }
}

// EPI: 0 = b-init, 1 = t1 (fp16), 2 = LCA update, 3 = out fp32
template <int EPI>
__global__ void __launch_bounds__(512, 1)
lca_gemm(const __half* __restrict__ Ah, const __half* __restrict__ Bh,
         int K, float* __restrict__ outp) {
    extern __shared__ __align__(256) char smem[];
    const uint32_t sbase = smem_u32(smem);
    const int tid = threadIdx.x;
    const int wid = tid >> 5;
    const int lid = tid & 31;
    const int warpM = wid >> 2;          // 0..3  (m offset 32)
    const int warpN = wid & 3;           // 0..3  (n offset 64)
    const int rowBase = blockIdx.y * 128;
    const int colBase = blockIdx.x * 256;
    const int KT = K >> 6;

    float acc[2][8][4];
    #pragma unroll
    for (int mi = 0; mi < 2; ++mi)
        #pragma unroll
        for (int ni = 0; ni < 8; ++ni)
            #pragma unroll
            for (int q = 0; q < 4; ++q) acc[mi][ni][q] = 0.f;

    stage_load(sbase, Ah, Bh, rowBase, colBase, 0, K, tid);
    cp_commit();
    stage_load(sbase + STAGE_BYTES, Ah, Bh, rowBase, colBase, 64, K, tid);
    cp_commit();

    const uint32_t lrow = (uint32_t)(lid & 15);
    const uint32_t lcol = (uint32_t)((lid >> 4) * 16);

    int sidx = 0;
    for (int kt = 0; kt < KT; ++kt) {
        cp_wait<1>();
        __syncthreads();

        if (kt + 2 < KT)
            stage_load(sbase + ((sidx + 2) % 3) * STAGE_BYTES,
                       Ah, Bh, rowBase, colBase, (kt + 2) * 64, K, tid);
        cp_commit();

        const uint32_t sb = sbase + sidx * STAGE_BYTES;
        const uint32_t aBase = sb + (uint32_t)(warpM * 32) * ROWB;
        const uint32_t bBase = sb + A_TILE + (uint32_t)(warpN * 64) * ROWB;

        #pragma unroll
        for (int ks = 0; ks < 4; ++ks) {
            const uint32_t kb = (uint32_t)(ks * 32) + lcol;
            uint32_t ah[2][4], bf[4][4];
            #pragma unroll
            for (int mi = 0; mi < 2; ++mi)
                ldsm4(ah[mi], aBase + (uint32_t)(mi * 16 + lrow) * ROWB + kb);
            #pragma unroll
            for (int nj = 0; nj < 4; ++nj)
                ldsm4(bf[nj], bBase + (uint32_t)(nj * 16 + lrow) * ROWB + kb);

            #pragma unroll
            for (int mi = 0; mi < 2; ++mi)
                #pragma unroll
                for (int ni = 0; ni < 8; ++ni) {
                    const int nj = ni >> 1, nr = ni & 1;
                    mma_f16(acc[mi][ni], ah[mi], bf[nj][nr], bf[nj][nr + 2]);
                }
        }
        __syncthreads();
        sidx = (sidx + 1) % 3;
    }

    // ------------------------------------------------------------ epilogue
    const int qrow = lid >> 2;
    const int qcol = (lid & 3) * 2;
    const int ldo = (EPI == 1 || EPI == 3) ? DMODEL : DLCA;

    #pragma unroll
    for (int mi = 0; mi < 2; ++mi) {
        #pragma unroll
        for (int ni = 0; ni < 8; ++ni) {
            const int r0 = rowBase + warpM * 32 + mi * 16 + qrow;
            const int c  = colBase + warpN * 64 + ni * 8 + qcol;
            #pragma unroll
            for (int h = 0; h < 2; ++h) {
                const int r = r0 + h * 8;
                const size_t base = (size_t)r * ldo + c;
                const float v0 = acc[mi][ni][2*h], v1 = acc[mi][ni][2*h + 1];
                if (EPI == 0) {
                    float u0 = BETA * v0, u1 = BETA * v1;
                    *reinterpret_cast<float2*>(g_b + base) = make_float2(v0, v1);
                    *reinterpret_cast<float2*>(g_u + base) = make_float2(u0, u1);
                    float a0 = fmaxf(u0 - LAMBDA, 0.f), a1 = fmaxf(u1 - LAMBDA, 0.f);
                    *reinterpret_cast<__half2*>(g_ahi + base) =
                        __halves2half2(__float2half_rn(a0), __float2half_rn(a1));
                } else if (EPI == 2) {
                    float2 uo = *reinterpret_cast<const float2*>(g_u + base);
                    float2 bv = *reinterpret_cast<const float2*>(g_b + base);
                    float2 dg = *reinterpret_cast<const float2*>(g_diagG + c);
                    float ao0 = fmaxf(uo.x - LAMBDA, 0.f), ao1 = fmaxf(uo.y - LAMBDA, 0.f);
                    float u0 = ONE_MB * uo.x + BETA * (bv.x - v0 + ao0 * dg.x);
                    float u1 = ONE_MB * uo.y + BETA * (bv.y - v1 + ao1 * dg.y);
                    *reinterpret_cast<float2*>(g_u + base) = make_float2(u0, u1);
                    float a0 = fmaxf(u0 - LAMBDA, 0.f), a1 = fmaxf(u1 - LAMBDA, 0.f);
                    *reinterpret_cast<__half2*>(g_ahi + base) =
                        __halves2half2(__float2half_rn(a0), __float2half_rn(a1));
                } else if (EPI == 1) {
                    *reinterpret_cast<__half2*>(g_t1hi + base) =
                        __halves2half2(__float2half_rn(v0), __float2half_rn(v1));
                } else {
                    *reinterpret_cast<float2*>(outp + base) = make_float2(v0, v1);
                }
            }
        }
    }
}

// ---------------------------------------------------------------- launch
extern "C" void kernel_launch(void* const* d_in, const int* in_sizes, int n_in,
                              void* d_out, int out_size) {
    const float* x = (const float*)d_in[0];   // [8192, 1024]
    const float* W = (const float*)d_in[1];   // [1024, 4096]
    float* out = (float*)d_out;               // [8192, 1024]

    __half *xhi, *Whi, *Wthi, *ahi, *t1hi;
    cudaGetSymbolAddress((void**)&xhi,  g_xhi);
    cudaGetSymbolAddress((void**)&Whi,  g_Whi);
    cudaGetSymbolAddress((void**)&Wthi, g_Wthi);
    cudaGetSymbolAddress((void**)&ahi,  g_ahi);
    cudaGetSymbolAddress((void**)&t1hi, g_t1hi);

    cudaFuncSetAttribute((const void*)lca_gemm<0>, cudaFuncAttributeMaxDynamicSharedMemorySize, SMEM_TOTAL);
    cudaFuncSetAttribute((const void*)lca_gemm<1>, cudaFuncAttributeMaxDynamicSharedMemorySize, SMEM_TOTAL);
    cudaFuncSetAttribute((const void*)lca_gemm<2>, cudaFuncAttributeMaxDynamicSharedMemorySize, SMEM_TOTAL);
    cudaFuncSetAttribute((const void*)lca_gemm<3>, cudaFuncAttributeMaxDynamicSharedMemorySize, SMEM_TOTAL);

    // prep
    half_kernel<<<(int)(((size_t)NROWS * DMODEL) / 1024), 256>>>(x, xhi);
    half_kernel<<<(int)(((size_t)DMODEL * DLCA) / 1024), 256>>>(W, Whi);
    transpose_kernel<<<dim3(DLCA / 32, DMODEL / 32), dim3(32, 8)>>>(W);
    zero_diag_kernel<<<DLCA / 256, 256>>>();
    diag_kernel<<<dim3(DLCA / 512, 16), 512>>>();

    // b = fp16(x)@W~ ; u = 0.1b ; a = fp16(relu(u - lambda))
    lca_gemm<0><<<dim3(DLCA / 256, NROWS / 128), 512, SMEM_TOTAL>>>(
        xhi, Wthi, DMODEL, nullptr);

    for (int it = 0; it < 9; ++it) {
        // t1 = a @ W~^T
        lca_gemm<1><<<dim3(DMODEL / 256, NROWS / 128), 512, SMEM_TOTAL>>>(
            ahi, Whi, DLCA, nullptr);
        // u = 0.9u + 0.1(b - t1@W~ + a*diagG~) ; a = fp16(relu(u - lambda))
        lca_gemm<2><<<dim3(DLCA / 256, NROWS / 128), 512, SMEM_TOTAL>>>(
            t1hi, Wthi, DMODEL, nullptr);
    }

    // out = a @ W~^T (fp32 out)
    lca_gemm<3><<<dim3(DMODEL / 256, NROWS / 128), 512, SMEM_TOTAL>>>(
        ahi, Whi, DLCA, out);
}